// round 13
// baseline (speedup 1.0000x reference)
#include <cuda_runtime.h>
#include <cuda_fp16.h>
#include <math.h>
#include <stdint.h>

#define NN   8192
#define EE   98304
#define ET   106496          /* EE + NN self loops */
#define K1   1024            /* inner dim of both GEMMs */
#define CC   256
#define NT1  2048            /* layer-1 combined output cols (xl|xr) */
#define NT2  512             /* layer-2 combined output cols */

/* ---------------- scratch (static device memory, no allocs) ----------------
   fp16 2-term split: C = Ah*Bh + Ah*Bl (Al*B dropped, ~2^-12 relative).
   A stores hi only [., K1]; B stores [hi|lo] [., 2*K1].                     */
__device__ __half g_Ax1[(size_t)NN * K1];
__device__ __half g_Bt1[(size_t)NT1 * 2 * K1];
__device__ float  g_C1 [(size_t)NN * NT1];
__device__ __half g_Ax2[(size_t)NN * K1];
__device__ __half g_Bt2[(size_t)NT2 * 2 * K1];
__device__ float  g_C2 [(size_t)NN * NT2];
__device__ int   g_counts [NN];
__device__ int   g_offsets[NN + 1];
__device__ int   g_cursor [NN];
__device__ int   g_csr    [ET];                        /* src node per CSR slot */

/* ---------------- PTX helpers ---------------- */
__device__ __forceinline__ uint32_t smem_u32(const void* p) {
    uint32_t a;
    asm("{ .reg .u64 t; cvta.to.shared.u64 t, %1; cvt.u32.u64 %0, t; }" : "=r"(a) : "l"(p));
    return a;
}
#define CP16(dst, src) asm volatile("cp.async.cg.shared.global [%0], [%1], 16;" :: "r"(dst), "l"(src) : "memory")
#define CP_COMMIT()    asm volatile("cp.async.commit_group;" ::: "memory")

__device__ __forceinline__ void ldsm4(uint32_t* r, uint32_t addr) {
    asm volatile("ldmatrix.sync.aligned.m8n8.x4.shared.b16 {%0,%1,%2,%3}, [%4];"
        : "=r"(r[0]), "=r"(r[1]), "=r"(r[2]), "=r"(r[3]) : "r"(addr));
}
__device__ __forceinline__ void mma16816(float* c, const uint32_t* a, const uint32_t* b) {
    asm volatile(
        "mma.sync.aligned.m16n8k16.row.col.f32.f16.f16.f32 "
        "{%0,%1,%2,%3}, {%4,%5,%6,%7}, {%8,%9}, {%0,%1,%2,%3};"
        : "+f"(c[0]), "+f"(c[1]), "+f"(c[2]), "+f"(c[3])
        : "r"(a[0]), "r"(a[1]), "r"(a[2]), "r"(a[3]), "r"(b[0]), "r"(b[1]));
}

/* ---------------- merged prologue: split_x + split_w x4 + counts init ------ */
#define PREP_BLOCKS 10784

__device__ __forceinline__ void split_w_body(
    const float* __restrict__ W, __half* __restrict__ Bt,
    int Nout, int n_off, int local, float* tbuf /* 32x33 smem */)
{
    int nblk = Nout / 32;
    int nx = (local % nblk) * 32;
    int kx = (local / nblk) * 32;
    int tx = threadIdx.x & 31, ty = threadIdx.x >> 5;   /* 32 x 8 */
#pragma unroll
    for (int i = 0; i < 32; i += 8)
        tbuf[(ty + i) * 33 + tx] = W[(size_t)(kx + ty + i) * Nout + nx + tx];
    __syncthreads();
#pragma unroll
    for (int i = 0; i < 32; i += 8) {
        float v = tbuf[tx * 33 + ty + i];
        int n = n_off + nx + ty + i, k = kx + tx;
        __half h = __float2half(v);
        Bt[(size_t)n * 2048 + k]        = h;
        Bt[(size_t)n * 2048 + 1024 + k] = __float2half(v - __half2float(h));
    }
}

__global__ void __launch_bounds__(256)
k_prep(const float* __restrict__ X,
       const float* __restrict__ Wl1, const float* __restrict__ Wr1,
       const float* __restrict__ Wl2, const float* __restrict__ Wr2)
{
    __shared__ float tbuf[32 * 33];
    const int b = blockIdx.x;
    if (b < 8192) {
        int idx = b * 256 + threadIdx.x;            /* NN*K1/4 items */
        int r = idx >> 8, kq = idx & 255;
        float4 v = *(const float4*)(X + ((size_t)r << 10) + kq * 4);
        size_t base = (size_t)r * 1024 + kq * 4;
        *(__half2*)&g_Ax1[base]     = __halves2half2(__float2half(v.x), __float2half(v.y));
        *(__half2*)&g_Ax1[base + 2] = __halves2half2(__float2half(v.z), __float2half(v.w));
    } else if (b < 9216) {
        split_w_body(Wl1, g_Bt1, 1024, 0,    b - 8192,  tbuf);
    } else if (b < 10240) {
        split_w_body(Wr1, g_Bt1, 1024, 1024, b - 9216,  tbuf);
    } else if (b < 10496) {
        split_w_body(Wl2, g_Bt2, 256,  0,    b - 10240, tbuf);
    } else if (b < 10752) {
        split_w_body(Wr2, g_Bt2, 256,  256,  b - 10496, tbuf);
    } else {
        int n = (b - 10752) * 256 + threadIdx.x;
        if (n < NN) g_counts[n] = 1;
    }
}

/* ---------------- CSR build (order-dependent chain) ---------------- */
__global__ void k_count(const int* __restrict__ ei) {
    int e = blockIdx.x * blockDim.x + threadIdx.x;
    if (e < EE) atomicAdd(&g_counts[ei[EE + e]], 1);
}
__global__ void k_scan() {
    __shared__ int warp_sums[32];
    int t = threadIdx.x, base = t * 8, v[8], s = 0;
#pragma unroll
    for (int i = 0; i < 8; i++) { v[i] = g_counts[base + i]; s += v[i]; }
    int lane = t & 31, w = t >> 5, ps = s;
#pragma unroll
    for (int o = 1; o < 32; o <<= 1) {
        int x = __shfl_up_sync(0xffffffffu, ps, o);
        if (lane >= o) ps += x;
    }
    if (lane == 31) warp_sums[w] = ps;
    __syncthreads();
    if (w == 0) {
        int x = warp_sums[lane];
#pragma unroll
        for (int o = 1; o < 32; o <<= 1) {
            int y = __shfl_up_sync(0xffffffffu, x, o);
            if (lane >= o) x += y;
        }
        warp_sums[lane] = x;
    }
    __syncthreads();
    int run = ps - s + (w > 0 ? warp_sums[w - 1] : 0);
#pragma unroll
    for (int i = 0; i < 8; i++) {
        g_offsets[base + i] = run;
        g_cursor [base + i] = run;
        run += v[i];
    }
    if (t == 1023) g_offsets[NN] = run;
}
__global__ void k_fill(const int* __restrict__ ei) {
    int idx = blockIdx.x * blockDim.x + threadIdx.x;
    if (idx >= ET) return;
    int src, dst;
    if (idx < EE) { src = ei[idx]; dst = ei[EE + idx]; }
    else          { src = dst = idx - EE; }
    g_csr[atomicAdd(&g_cursor[dst], 1)] = src;
}

/* ---------------- mma.sync fp16 2-term GEMM, A-reuse ----------------
   C[M, Ntot] = Ah @ (Bh|Bl)^T.  Each k-chunk loads A ONCE and both B
   halves, using the A fragments for Bh and Bl mma -> A traffic halved.
   CTA 128x128, warps 64x32, BK=32, NST=3, one sync per chunk.          */
#define BM   128
#define BN   128
#define BK   32
#define NST  3
#define NIT  32                  /* K1 / BK */
#define STR  20                  /* u32 stride per row (16 kpairs + 4 pad) */
#define A_U32 (BM * STR)
#define B_U32 (2 * BN * STR)     /* Bh rows 0..127, Bl rows 128..255 */
#define STAGE_BYTES ((A_U32 + B_U32) * 4)
#define GEMM_SMEM (NST * STAGE_BYTES)

__global__ void __launch_bounds__(256, 2)
k_gemm_tc(const __half* __restrict__ A, const __half* __restrict__ B,
          float* __restrict__ C, int Ntot)
{
    extern __shared__ char smem[];
    const uint32_t sb = smem_u32(smem);
    const int tid = threadIdx.x;
    const int lane = tid & 31;
    const int w = tid >> 5;
    const int wm = (w & 1) * 64;
    const int wn = (w >> 1) * 32;
    const int row0 = blockIdx.y * BM;
    const int col0 = blockIdx.x * BN;
    const int K2 = 2 * K1;

    float acc[4][4][4];
#pragma unroll
    for (int i = 0; i < 4; i++)
#pragma unroll
        for (int j = 0; j < 4; j++)
#pragma unroll
            for (int q = 0; q < 4; q++) acc[i][j][q] = 0.f;

    const int msel = lane >> 3, within = lane & 7;
    const int a_r = (msel & 1) * 8 + within;
    const int a_c = (msel >> 1) * 4;
    const int b_r = (msel >> 1) * 8 + within;
    const int b_c = (msel & 1) * 4;

    /* load one BK=32 chunk: A once (128 rows x 64B) + Bh + Bl (256 x 64B) */
    auto load_chunk = [&](int ch) {
        int k0 = ch * BK;
        uint32_t sa = sb + (ch % NST) * STAGE_BYTES;
        uint32_t sB = sa + A_U32 * 4;
#pragma unroll
        for (int i = 0; i < 2; i++) {
            int lin = tid + i * 256, r = lin >> 2, j = lin & 3;
            CP16(sa + r * (STR * 4) + j * 16,
                 __cvta_generic_to_global(A + (size_t)(row0 + r) * K1 + k0 + j * 8));
        }
#pragma unroll
        for (int i = 0; i < 4; i++) {
            int lin = tid + i * 256, vr = lin >> 2, j = lin & 3;
            int r = vr & 127, lo = vr >> 7;           /* 0 = hi, 1 = lo half */
            CP16(sB + vr * (STR * 4) + j * 16,
                 __cvta_generic_to_global(B + (size_t)(col0 + r) * K2 + lo * K1 + k0 + j * 8));
        }
        CP_COMMIT();
    };

    load_chunk(0); load_chunk(1);

    for (int it = 0; it < NIT; it++) {
        if (it < NIT - 1) asm volatile("cp.async.wait_group 1;" ::: "memory");
        else              asm volatile("cp.async.wait_group 0;" ::: "memory");
        __syncthreads();
        if (it + 2 < NIT) load_chunk(it + 2);   /* slot (it+2)%3 = slot of it-1 */

        uint32_t sa = sb + (it % NST) * STAGE_BYTES;
        uint32_t sB = sa + A_U32 * 4;
#pragma unroll
        for (int kk = 0; kk < 2; kk++) {
            uint32_t af[4][4], bfh[4][2], bfl[4][2];
#pragma unroll
            for (int mf = 0; mf < 4; mf++)
                ldsm4(af[mf], sa + ((wm + mf * 16 + a_r) * STR + kk * 8 + a_c) * 4);
#pragma unroll
            for (int p = 0; p < 2; p++) {
                uint32_t t4[4];
                ldsm4(t4, sB + ((wn + p * 16 + b_r) * STR + kk * 8 + b_c) * 4);
                bfh[2 * p][0] = t4[0]; bfh[2 * p][1] = t4[1];
                bfh[2 * p + 1][0] = t4[2]; bfh[2 * p + 1][1] = t4[3];
                ldsm4(t4, sB + ((128 + wn + p * 16 + b_r) * STR + kk * 8 + b_c) * 4);
                bfl[2 * p][0] = t4[0]; bfl[2 * p][1] = t4[1];
                bfl[2 * p + 1][0] = t4[2]; bfl[2 * p + 1][1] = t4[3];
            }
#pragma unroll
            for (int mf = 0; mf < 4; mf++)
#pragma unroll
                for (int nf = 0; nf < 4; nf++)
                    mma16816(acc[mf][nf], af[mf], bfh[nf]);
#pragma unroll
            for (int mf = 0; mf < 4; mf++)
#pragma unroll
                for (int nf = 0; nf < 4; nf++)
                    mma16816(acc[mf][nf], af[mf], bfl[nf]);
        }
    }

    const int r = lane >> 2, q = lane & 3;
#pragma unroll
    for (int mf = 0; mf < 4; mf++) {
        int rg = row0 + wm + mf * 16 + r;
#pragma unroll
        for (int nf = 0; nf < 4; nf++) {
            float* p0 = C + (size_t)rg * Ntot + col0 + wn + nf * 8 + q * 2;
            *(float2*)p0 = make_float2(acc[mf][nf][0], acc[mf][nf][1]);
            *(float2*)(p0 + (size_t)8 * Ntot) = make_float2(acc[mf][nf][2], acc[mf][nf][3]);
        }
    }
}

/* ---------------- fused layer-1: warp per (node, head) -------------------- */
__global__ void __launch_bounds__(256)
k_fused1(const float* __restrict__ att, const float* __restrict__ bias)
{
    const int w = threadIdx.x >> 5;
    const int lane = threadIdx.x & 31;
    const int n = blockIdx.x * 2 + (w >> 2);
    const int h = w & 3;
    const int cA = h * 256 + lane * 4;
    const int cB = cA + 128;

    const float* base1 = g_C1;
    const float4 xr0 = *(const float4*)&base1[(size_t)n * NT1 + 1024 + cA];
    const float4 xr1 = *(const float4*)&base1[(size_t)n * NT1 + 1024 + cB];
    const float4 at0 = *(const float4*)&att[cA];
    const float4 at1 = *(const float4*)&att[cB];

    float4 num0 = make_float4(0.f, 0.f, 0.f, 0.f);
    float4 num1 = make_float4(0.f, 0.f, 0.f, 0.f);
    float den = 0.f;
    const int beg = g_offsets[n], end = g_offsets[n + 1];

    for (int j = beg; j < end; j++) {
        int s = g_csr[j];
        const float* xl_row = &base1[(size_t)s * NT1];
        float4 xl0 = *(const float4*)&xl_row[cA];
        float4 xl1 = *(const float4*)&xl_row[cB];
        float v0 = xl0.x + xr0.x, v1 = xl0.y + xr0.y, v2 = xl0.z + xr0.z, v3 = xl0.w + xr0.w;
        float u0 = xl1.x + xr1.x, u1 = xl1.y + xr1.y, u2 = xl1.z + xr1.z, u3 = xl1.w + xr1.w;
        v0 = (v0 > 0.f) ? v0 : 0.2f * v0;  v1 = (v1 > 0.f) ? v1 : 0.2f * v1;
        v2 = (v2 > 0.f) ? v2 : 0.2f * v2;  v3 = (v3 > 0.f) ? v3 : 0.2f * v3;
        u0 = (u0 > 0.f) ? u0 : 0.2f * u0;  u1 = (u1 > 0.f) ? u1 : 0.2f * u1;
        u2 = (u2 > 0.f) ? u2 : 0.2f * u2;  u3 = (u3 > 0.f) ? u3 : 0.2f * u3;
        float p = fmaf(v0, at0.x, fmaf(v1, at0.y, fmaf(v2, at0.z, v3 * at0.w)))
                + fmaf(u0, at1.x, fmaf(u1, at1.y, fmaf(u2, at1.z, u3 * at1.w)));
#pragma unroll
        for (int o = 16; o > 0; o >>= 1)
            p += __shfl_xor_sync(0xffffffffu, p, o);
        float ex = __expf(p);
        den += ex;
        num0.x = fmaf(ex, xl0.x, num0.x); num0.y = fmaf(ex, xl0.y, num0.y);
        num0.z = fmaf(ex, xl0.z, num0.z); num0.w = fmaf(ex, xl0.w, num0.w);
        num1.x = fmaf(ex, xl1.x, num1.x); num1.y = fmaf(ex, xl1.y, num1.y);
        num1.z = fmaf(ex, xl1.z, num1.z); num1.w = fmaf(ex, xl1.w, num1.w);
    }

    const float4 bA = *(const float4*)&bias[cA];
    const float4 bB = *(const float4*)&bias[cB];
    const float inv = 1.f / den;
    float r0 = fmaxf(fmaf(num0.x, inv, bA.x), 0.f);
    float r1 = fmaxf(fmaf(num0.y, inv, bA.y), 0.f);
    float r2 = fmaxf(fmaf(num0.z, inv, bA.z), 0.f);
    float r3 = fmaxf(fmaf(num0.w, inv, bA.w), 0.f);
    float s0 = fmaxf(fmaf(num1.x, inv, bB.x), 0.f);
    float s1 = fmaxf(fmaf(num1.y, inv, bB.y), 0.f);
    float s2 = fmaxf(fmaf(num1.z, inv, bB.z), 0.f);
    float s3 = fmaxf(fmaf(num1.w, inv, bB.w), 0.f);

    /* layer-2 A operand: fp16 hi only */
    size_t baseA = (size_t)n * 1024 + cA;
    size_t baseB = (size_t)n * 1024 + cB;
    *(__half2*)&g_Ax2[baseA]     = __halves2half2(__float2half(r0), __float2half(r1));
    *(__half2*)&g_Ax2[baseA + 2] = __halves2half2(__float2half(r2), __float2half(r3));
    *(__half2*)&g_Ax2[baseB]     = __halves2half2(__float2half(s0), __float2half(s1));
    *(__half2*)&g_Ax2[baseB + 2] = __halves2half2(__float2half(s2), __float2half(s3));
}

/* ---------------- fused layer-2: warp per node (1 head, 256 cols) --------- */
__global__ void __launch_bounds__(256)
k_fused2(const float* __restrict__ att, const float* __restrict__ bias,
         float* __restrict__ out)
{
    const int w = threadIdx.x >> 5;
    const int lane = threadIdx.x & 31;
    const int n = blockIdx.x * 8 + w;
    const int cA = lane * 4;
    const int cB = cA + 128;

    const float* base2 = g_C2;
    const float4 xr0 = *(const float4*)&base2[(size_t)n * NT2 + 256 + cA];
    const float4 xr1 = *(const float4*)&base2[(size_t)n * NT2 + 256 + cB];
    const float4 at0 = *(const float4*)&att[cA];
    const float4 at1 = *(const float4*)&att[cB];

    float4 num0 = make_float4(0.f, 0.f, 0.f, 0.f);
    float4 num1 = make_float4(0.f, 0.f, 0.f, 0.f);
    float den = 0.f;
    const int beg = g_offsets[n], end = g_offsets[n + 1];

    for (int j = beg; j < end; j++) {
        int s = g_csr[j];
        const float* xl_row = &base2[(size_t)s * NT2];
        float4 xl0 = *(const float4*)&xl_row[cA];
        float4 xl1 = *(const float4*)&xl_row[cB];
        float v0 = xl0.x + xr0.x, v1 = xl0.y + xr0.y, v2 = xl0.z + xr0.z, v3 = xl0.w + xr0.w;
        float u0 = xl1.x + xr1.x, u1 = xl1.y + xr1.y, u2 = xl1.z + xr1.z, u3 = xl1.w + xr1.w;
        v0 = (v0 > 0.f) ? v0 : 0.2f * v0;  v1 = (v1 > 0.f) ? v1 : 0.2f * v1;
        v2 = (v2 > 0.f) ? v2 : 0.2f * v2;  v3 = (v3 > 0.f) ? v3 : 0.2f * v3;
        u0 = (u0 > 0.f) ? u0 : 0.2f * u0;  u1 = (u1 > 0.f) ? u1 : 0.2f * u1;
        u2 = (u2 > 0.f) ? u2 : 0.2f * u2;  u3 = (u3 > 0.f) ? u3 : 0.2f * u3;
        float p = fmaf(v0, at0.x, fmaf(v1, at0.y, fmaf(v2, at0.z, v3 * at0.w)))
                + fmaf(u0, at1.x, fmaf(u1, at1.y, fmaf(u2, at1.z, u3 * at1.w)));
#pragma unroll
        for (int o = 16; o > 0; o >>= 1)
            p += __shfl_xor_sync(0xffffffffu, p, o);
        float ex = __expf(p);
        den += ex;
        num0.x = fmaf(ex, xl0.x, num0.x); num0.y = fmaf(ex, xl0.y, num0.y);
        num0.z = fmaf(ex, xl0.z, num0.z); num0.w = fmaf(ex, xl0.w, num0.w);
        num1.x = fmaf(ex, xl1.x, num1.x); num1.y = fmaf(ex, xl1.y, num1.y);
        num1.z = fmaf(ex, xl1.z, num1.z); num1.w = fmaf(ex, xl1.w, num1.w);
    }

    const float4 bA = *(const float4*)&bias[cA];
    const float4 bB = *(const float4*)&bias[cB];
    const float inv = 1.f / den;
    float4 rA, rB;
    rA.x = fmaxf(fmaf(num0.x, inv, bA.x), 0.f);
    rA.y = fmaxf(fmaf(num0.y, inv, bA.y), 0.f);
    rA.z = fmaxf(fmaf(num0.z, inv, bA.z), 0.f);
    rA.w = fmaxf(fmaf(num0.w, inv, bA.w), 0.f);
    rB.x = fmaxf(fmaf(num1.x, inv, bB.x), 0.f);
    rB.y = fmaxf(fmaf(num1.y, inv, bB.y), 0.f);
    rB.z = fmaxf(fmaf(num1.z, inv, bB.z), 0.f);
    rB.w = fmaxf(fmaf(num1.w, inv, bB.w), 0.f);
    *(float4*)&out[(size_t)n * CC + cA] = rA;
    *(float4*)&out[(size_t)n * CC + cB] = rB;
}

/* ---------------- launch ---------------- */
extern "C" void kernel_launch(void* const* d_in, const int* in_sizes, int n_in,
                              void* d_out, int out_size)
{
    const float* x    = (const float*)d_in[0];
    const int*   ei   = (const int*)  d_in[1];
    const float* Wl1  = (const float*)d_in[2];
    const float* Wr1  = (const float*)d_in[3];
    const float* att1 = (const float*)d_in[4];
    const float* b1   = (const float*)d_in[5];
    const float* Wl2  = (const float*)d_in[6];
    const float* Wr2  = (const float*)d_in[7];
    const float* att2 = (const float*)d_in[8];
    const float* b2   = (const float*)d_in[9];
    float* out = (float*)d_out;

    __half *p_Ax1, *p_Bt1, *p_Ax2, *p_Bt2;
    float *p_C1, *p_C2;
    cudaGetSymbolAddress((void**)&p_Ax1, g_Ax1);
    cudaGetSymbolAddress((void**)&p_Bt1, g_Bt1);
    cudaGetSymbolAddress((void**)&p_C1,  g_C1);
    cudaGetSymbolAddress((void**)&p_Ax2, g_Ax2);
    cudaGetSymbolAddress((void**)&p_Bt2, g_Bt2);
    cudaGetSymbolAddress((void**)&p_C2,  g_C2);

    cudaFuncSetAttribute(k_gemm_tc, cudaFuncAttributeMaxDynamicSharedMemorySize, GEMM_SMEM);

    /* merged prologue + CSR chain */
    k_prep<<<PREP_BLOCKS, 256>>>(x, Wl1, Wr1, Wl2, Wr2);
    k_count<<<EE / 256, 256>>>(ei);
    k_scan<<<1, 1024>>>();
    k_fill<<<(ET + 255) / 256, 256>>>(ei);

    /* layer 1 */
    k_gemm_tc<<<dim3(NT1 / BN, NN / BM), 256, GEMM_SMEM>>>(p_Ax1, p_Bt1, p_C1, NT1);
    k_fused1<<<NN / 2, 256>>>(att1, b1);

    /* layer 2 */
    k_gemm_tc<<<dim3(NT2 / BN, NN / BM), 256, GEMM_SMEM>>>(p_Ax2, p_Bt2, p_C2, NT2);
    k_fused2<<<NN / 8, 256>>>(att2, b2, out);
}

// round 14
// speedup vs baseline: 1.0227x; 1.0227x over previous
#include <cuda_runtime.h>
#include <cuda_fp16.h>
#include <math.h>
#include <stdint.h>

#define NN   8192
#define EE   98304
#define ET   106496          /* EE + NN self loops */
#define K1   1024            /* inner dim of both GEMMs */
#define CC   256
#define NT1  2048            /* layer-1 combined output cols (xl|xr) */
#define NT2  512             /* layer-2 combined output cols */

/* ---------------- scratch (static device memory, no allocs) ----------------
   fp16 2-term split: C = Ah*Bh + Ah*Bl (Al*B dropped, ~2^-12 relative).
   A stores hi only [., K1]; B stores [hi|lo] [., 2*K1].                     */
__device__ __half g_Ax1[(size_t)NN * K1];
__device__ __half g_Bt1[(size_t)NT1 * 2 * K1];
__device__ float  g_C1 [(size_t)NN * NT1];
__device__ __half g_Ax2[(size_t)NN * K1];
__device__ __half g_Bt2[(size_t)NT2 * 2 * K1];
__device__ float  g_C2 [(size_t)NN * NT2];
__device__ int   g_counts [NN];     /* zero at entry; scan resets to zero    */
__device__ int   g_offsets[NN + 1];
__device__ int   g_cursor [NN];
__device__ int   g_csr    [ET];     /* src node per CSR slot */

/* ---------------- PTX helpers ---------------- */
__device__ __forceinline__ uint32_t smem_u32(const void* p) {
    uint32_t a;
    asm("{ .reg .u64 t; cvta.to.shared.u64 t, %1; cvt.u32.u64 %0, t; }" : "=r"(a) : "l"(p));
    return a;
}
#define CP16(dst, src) asm volatile("cp.async.cg.shared.global [%0], [%1], 16;" :: "r"(dst), "l"(src) : "memory")
#define CP_COMMIT()    asm volatile("cp.async.commit_group;" ::: "memory")

__device__ __forceinline__ void ldsm4(uint32_t* r, uint32_t addr) {
    asm volatile("ldmatrix.sync.aligned.m8n8.x4.shared.b16 {%0,%1,%2,%3}, [%4];"
        : "=r"(r[0]), "=r"(r[1]), "=r"(r[2]), "=r"(r[3]) : "r"(addr));
}
__device__ __forceinline__ void mma16816(float* c, const uint32_t* a, const uint32_t* b) {
    asm volatile(
        "mma.sync.aligned.m16n8k16.row.col.f32.f16.f16.f32 "
        "{%0,%1,%2,%3}, {%4,%5,%6,%7}, {%8,%9}, {%0,%1,%2,%3};"
        : "+f"(c[0]), "+f"(c[1]), "+f"(c[2]), "+f"(c[3])
        : "r"(a[0]), "r"(a[1]), "r"(a[2]), "r"(a[3]), "r"(b[0]), "r"(b[1]));
}

/* ---------------- merged prologue ----------------
   blocks [0, 8192)        : split_x  (X -> g_Ax1 fp16 hi)
   blocks [8192, 9216)     : split_w Wl1 -> g_Bt1 @ 0
   blocks [9216, 10240)    : split_w Wr1 -> g_Bt1 @ 1024
   blocks [10240, 10496)   : split_w Wl2 -> g_Bt2 @ 0
   blocks [10496, 10752)   : split_w Wr2 -> g_Bt2 @ 256
   blocks [10752, 11136)   : edge-count atomicAdd (counts start at 0;
                             self loops added inside k_scan)               */
#define PREP_BLOCKS 11136

__device__ __forceinline__ void split_w_body(
    const float* __restrict__ W, __half* __restrict__ Bt,
    int Nout, int n_off, int local, float* tbuf /* 32x33 smem */)
{
    int nblk = Nout / 32;
    int nx = (local % nblk) * 32;
    int kx = (local / nblk) * 32;
    int tx = threadIdx.x & 31, ty = threadIdx.x >> 5;   /* 32 x 8 */
#pragma unroll
    for (int i = 0; i < 32; i += 8)
        tbuf[(ty + i) * 33 + tx] = W[(size_t)(kx + ty + i) * Nout + nx + tx];
    __syncthreads();
#pragma unroll
    for (int i = 0; i < 32; i += 8) {
        float v = tbuf[tx * 33 + ty + i];
        int n = n_off + nx + ty + i, k = kx + tx;
        __half h = __float2half(v);
        Bt[(size_t)n * 2048 + k]        = h;
        Bt[(size_t)n * 2048 + 1024 + k] = __float2half(v - __half2float(h));
    }
}

__global__ void __launch_bounds__(256)
k_prep(const float* __restrict__ X,
       const float* __restrict__ Wl1, const float* __restrict__ Wr1,
       const float* __restrict__ Wl2, const float* __restrict__ Wr2,
       const int* __restrict__ ei)
{
    __shared__ float tbuf[32 * 33];
    const int b = blockIdx.x;
    if (b < 8192) {
        int idx = b * 256 + threadIdx.x;            /* NN*K1/4 items */
        int r = idx >> 8, kq = idx & 255;
        float4 v = *(const float4*)(X + ((size_t)r << 10) + kq * 4);
        size_t base = (size_t)r * 1024 + kq * 4;
        *(__half2*)&g_Ax1[base]     = __halves2half2(__float2half(v.x), __float2half(v.y));
        *(__half2*)&g_Ax1[base + 2] = __halves2half2(__float2half(v.z), __float2half(v.w));
    } else if (b < 9216) {
        split_w_body(Wl1, g_Bt1, 1024, 0,    b - 8192,  tbuf);
    } else if (b < 10240) {
        split_w_body(Wr1, g_Bt1, 1024, 1024, b - 9216,  tbuf);
    } else if (b < 10496) {
        split_w_body(Wl2, g_Bt2, 256,  0,    b - 10240, tbuf);
    } else if (b < 10752) {
        split_w_body(Wr2, g_Bt2, 256,  256,  b - 10496, tbuf);
    } else {
        int e = (b - 10752) * 256 + threadIdx.x;
        if (e < EE) atomicAdd(&g_counts[ei[EE + e]], 1);
    }
}

/* ---------------- CSR build (order-dependent chain) ----------------
   scan adds the self-loop (+1/node) while reading, and resets counts
   to zero so the next replay's k_prep atomicAdds start from 0.        */
__global__ void k_scan() {
    __shared__ int warp_sums[32];
    int t = threadIdx.x, base = t * 8, v[8], s = 0;
#pragma unroll
    for (int i = 0; i < 8; i++) {
        v[i] = g_counts[base + i] + 1;     /* +1 = self loop */
        g_counts[base + i] = 0;            /* reset for next replay */
        s += v[i];
    }
    int lane = t & 31, w = t >> 5, ps = s;
#pragma unroll
    for (int o = 1; o < 32; o <<= 1) {
        int x = __shfl_up_sync(0xffffffffu, ps, o);
        if (lane >= o) ps += x;
    }
    if (lane == 31) warp_sums[w] = ps;
    __syncthreads();
    if (w == 0) {
        int x = warp_sums[lane];
#pragma unroll
        for (int o = 1; o < 32; o <<= 1) {
            int y = __shfl_up_sync(0xffffffffu, x, o);
            if (lane >= o) x += y;
        }
        warp_sums[lane] = x;
    }
    __syncthreads();
    int run = ps - s + (w > 0 ? warp_sums[w - 1] : 0);
#pragma unroll
    for (int i = 0; i < 8; i++) {
        g_offsets[base + i] = run;
        g_cursor [base + i] = run;
        run += v[i];
    }
    if (t == 1023) g_offsets[NN] = run;
}
__global__ void k_fill(const int* __restrict__ ei) {
    int idx = blockIdx.x * blockDim.x + threadIdx.x;
    if (idx >= ET) return;
    int src, dst;
    if (idx < EE) { src = ei[idx]; dst = ei[EE + idx]; }
    else          { src = dst = idx - EE; }
    g_csr[atomicAdd(&g_cursor[dst], 1)] = src;
}

/* ---------------- mma.sync fp16 2-term GEMM (R12 config, the 376.7 best) --
   C[M, Ntot] = Ah @ (Bh|Bl)^T, virtual K2 = 2*K1.
   chunks [0,16): Ah x Bh ; [16,32): Ah x Bl.
   CTA 128x128, warps 64x32, BK=64, NST=3, one sync per chunk.            */
#define BM   128
#define BN   128
#define BK   64
#define NST  3
#define NIT  32                  /* 2*K1 / BK */
#define STR  36                  /* u32 stride per row (32 kpairs + 4 pad) */
#define A_U32 (BM * STR)
#define B_U32 (BN * STR)
#define STAGE_BYTES ((A_U32 + B_U32) * 4)
#define GEMM_SMEM (NST * STAGE_BYTES)

__global__ void __launch_bounds__(256, 2)
k_gemm_tc(const __half* __restrict__ A, const __half* __restrict__ B,
          float* __restrict__ C, int Ntot)
{
    extern __shared__ char smem[];
    const uint32_t sb = smem_u32(smem);
    const int tid = threadIdx.x;
    const int lane = tid & 31;
    const int w = tid >> 5;
    const int wm = (w & 1) * 64;
    const int wn = (w >> 1) * 32;
    const int row0 = blockIdx.y * BM;
    const int col0 = blockIdx.x * BN;
    const int K2 = 2 * K1;

    float acc[4][4][4];
#pragma unroll
    for (int i = 0; i < 4; i++)
#pragma unroll
        for (int j = 0; j < 4; j++)
#pragma unroll
            for (int q = 0; q < 4; q++) acc[i][j][q] = 0.f;

    const int msel = lane >> 3, within = lane & 7;
    const int a_r = (msel & 1) * 8 + within;
    const int a_c = (msel >> 1) * 4;
    const int b_r = (msel >> 1) * 8 + within;
    const int b_c = (msel & 1) * 4;

    auto load_chunk = [&](int ch) {
        int a_k0 = (ch & 15) * BK;      /* A hi reused across both passes */
        int b_k0 = ch * BK;             /* B walks hi then lo             */
        uint32_t sa = sb + (ch % NST) * STAGE_BYTES;
        uint32_t sB = sa + A_U32 * 4;
#pragma unroll
        for (int i = 0; i < 4; i++) {
            int lin = tid + i * 256, r = lin >> 3, j = lin & 7;
            CP16(sa + r * (STR * 4) + j * 16,
                 __cvta_generic_to_global(A + (size_t)(row0 + r) * K1 + a_k0 + j * 8));
        }
#pragma unroll
        for (int i = 0; i < 4; i++) {
            int lin = tid + i * 256, r = lin >> 3, j = lin & 7;
            CP16(sB + r * (STR * 4) + j * 16,
                 __cvta_generic_to_global(B + (size_t)(col0 + r) * K2 + b_k0 + j * 8));
        }
        CP_COMMIT();
    };

    load_chunk(0); load_chunk(1);

    for (int it = 0; it < NIT; it++) {
        if (it < NIT - 1) asm volatile("cp.async.wait_group 1;" ::: "memory");
        else              asm volatile("cp.async.wait_group 0;" ::: "memory");
        __syncthreads();
        if (it + 2 < NIT) load_chunk(it + 2);

        uint32_t sa = sb + (it % NST) * STAGE_BYTES;
        uint32_t sB = sa + A_U32 * 4;
#pragma unroll
        for (int kk = 0; kk < 4; kk++) {
            uint32_t af[4][4], bf[4][2];
#pragma unroll
            for (int mf = 0; mf < 4; mf++)
                ldsm4(af[mf], sa + ((wm + mf * 16 + a_r) * STR + kk * 8 + a_c) * 4);
#pragma unroll
            for (int p = 0; p < 2; p++) {
                uint32_t t4[4];
                ldsm4(t4, sB + ((wn + p * 16 + b_r) * STR + kk * 8 + b_c) * 4);
                bf[2 * p][0] = t4[0]; bf[2 * p][1] = t4[1];
                bf[2 * p + 1][0] = t4[2]; bf[2 * p + 1][1] = t4[3];
            }
#pragma unroll
            for (int mf = 0; mf < 4; mf++)
#pragma unroll
                for (int nf = 0; nf < 4; nf++)
                    mma16816(acc[mf][nf], af[mf], bf[nf]);
        }
    }

    const int r = lane >> 2, q = lane & 3;
#pragma unroll
    for (int mf = 0; mf < 4; mf++) {
        int rg = row0 + wm + mf * 16 + r;
#pragma unroll
        for (int nf = 0; nf < 4; nf++) {
            float* p0 = C + (size_t)rg * Ntot + col0 + wn + nf * 8 + q * 2;
            *(float2*)p0 = make_float2(acc[mf][nf][0], acc[mf][nf][1]);
            *(float2*)(p0 + (size_t)8 * Ntot) = make_float2(acc[mf][nf][2], acc[mf][nf][3]);
        }
    }
}

/* ---------------- fused layer-1: warp per (node, head) -------------------- */
__global__ void __launch_bounds__(256)
k_fused1(const float* __restrict__ att, const float* __restrict__ bias)
{
    const int w = threadIdx.x >> 5;
    const int lane = threadIdx.x & 31;
    const int n = blockIdx.x * 2 + (w >> 2);
    const int h = w & 3;
    const int cA = h * 256 + lane * 4;
    const int cB = cA + 128;

    const float* base1 = g_C1;
    const float4 xr0 = *(const float4*)&base1[(size_t)n * NT1 + 1024 + cA];
    const float4 xr1 = *(const float4*)&base1[(size_t)n * NT1 + 1024 + cB];
    const float4 at0 = *(const float4*)&att[cA];
    const float4 at1 = *(const float4*)&att[cB];

    float4 num0 = make_float4(0.f, 0.f, 0.f, 0.f);
    float4 num1 = make_float4(0.f, 0.f, 0.f, 0.f);
    float den = 0.f;
    const int beg = g_offsets[n], end = g_offsets[n + 1];

    for (int j = beg; j < end; j++) {
        int s = g_csr[j];
        const float* xl_row = &base1[(size_t)s * NT1];
        float4 xl0 = *(const float4*)&xl_row[cA];
        float4 xl1 = *(const float4*)&xl_row[cB];
        float v0 = xl0.x + xr0.x, v1 = xl0.y + xr0.y, v2 = xl0.z + xr0.z, v3 = xl0.w + xr0.w;
        float u0 = xl1.x + xr1.x, u1 = xl1.y + xr1.y, u2 = xl1.z + xr1.z, u3 = xl1.w + xr1.w;
        v0 = (v0 > 0.f) ? v0 : 0.2f * v0;  v1 = (v1 > 0.f) ? v1 : 0.2f * v1;
        v2 = (v2 > 0.f) ? v2 : 0.2f * v2;  v3 = (v3 > 0.f) ? v3 : 0.2f * v3;
        u0 = (u0 > 0.f) ? u0 : 0.2f * u0;  u1 = (u1 > 0.f) ? u1 : 0.2f * u1;
        u2 = (u2 > 0.f) ? u2 : 0.2f * u2;  u3 = (u3 > 0.f) ? u3 : 0.2f * u3;
        float p = fmaf(v0, at0.x, fmaf(v1, at0.y, fmaf(v2, at0.z, v3 * at0.w)))
                + fmaf(u0, at1.x, fmaf(u1, at1.y, fmaf(u2, at1.z, u3 * at1.w)));
#pragma unroll
        for (int o = 16; o > 0; o >>= 1)
            p += __shfl_xor_sync(0xffffffffu, p, o);
        float ex = __expf(p);
        den += ex;
        num0.x = fmaf(ex, xl0.x, num0.x); num0.y = fmaf(ex, xl0.y, num0.y);
        num0.z = fmaf(ex, xl0.z, num0.z); num0.w = fmaf(ex, xl0.w, num0.w);
        num1.x = fmaf(ex, xl1.x, num1.x); num1.y = fmaf(ex, xl1.y, num1.y);
        num1.z = fmaf(ex, xl1.z, num1.z); num1.w = fmaf(ex, xl1.w, num1.w);
    }

    const float4 bA = *(const float4*)&bias[cA];
    const float4 bB = *(const float4*)&bias[cB];
    const float inv = 1.f / den;
    float r0 = fmaxf(fmaf(num0.x, inv, bA.x), 0.f);
    float r1 = fmaxf(fmaf(num0.y, inv, bA.y), 0.f);
    float r2 = fmaxf(fmaf(num0.z, inv, bA.z), 0.f);
    float r3 = fmaxf(fmaf(num0.w, inv, bA.w), 0.f);
    float s0 = fmaxf(fmaf(num1.x, inv, bB.x), 0.f);
    float s1 = fmaxf(fmaf(num1.y, inv, bB.y), 0.f);
    float s2 = fmaxf(fmaf(num1.z, inv, bB.z), 0.f);
    float s3 = fmaxf(fmaf(num1.w, inv, bB.w), 0.f);

    /* layer-2 A operand: fp16 hi only */
    size_t baseA = (size_t)n * 1024 + cA;
    size_t baseB = (size_t)n * 1024 + cB;
    *(__half2*)&g_Ax2[baseA]     = __halves2half2(__float2half(r0), __float2half(r1));
    *(__half2*)&g_Ax2[baseA + 2] = __halves2half2(__float2half(r2), __float2half(r3));
    *(__half2*)&g_Ax2[baseB]     = __halves2half2(__float2half(s0), __float2half(s1));
    *(__half2*)&g_Ax2[baseB + 2] = __halves2half2(__float2half(s2), __float2half(s3));
}

/* ---------------- fused layer-2: warp per node (1 head, 256 cols) --------- */
__global__ void __launch_bounds__(256)
k_fused2(const float* __restrict__ att, const float* __restrict__ bias,
         float* __restrict__ out)
{
    const int w = threadIdx.x >> 5;
    const int lane = threadIdx.x & 31;
    const int n = blockIdx.x * 8 + w;
    const int cA = lane * 4;
    const int cB = cA + 128;

    const float* base2 = g_C2;
    const float4 xr0 = *(const float4*)&base2[(size_t)n * NT2 + 256 + cA];
    const float4 xr1 = *(const float4*)&base2[(size_t)n * NT2 + 256 + cB];
    const float4 at0 = *(const float4*)&att[cA];
    const float4 at1 = *(const float4*)&att[cB];

    float4 num0 = make_float4(0.f, 0.f, 0.f, 0.f);
    float4 num1 = make_float4(0.f, 0.f, 0.f, 0.f);
    float den = 0.f;
    const int beg = g_offsets[n], end = g_offsets[n + 1];

    for (int j = beg; j < end; j++) {
        int s = g_csr[j];
        const float* xl_row = &base2[(size_t)s * NT2];
        float4 xl0 = *(const float4*)&xl_row[cA];
        float4 xl1 = *(const float4*)&xl_row[cB];
        float v0 = xl0.x + xr0.x, v1 = xl0.y + xr0.y, v2 = xl0.z + xr0.z, v3 = xl0.w + xr0.w;
        float u0 = xl1.x + xr1.x, u1 = xl1.y + xr1.y, u2 = xl1.z + xr1.z, u3 = xl1.w + xr1.w;
        v0 = (v0 > 0.f) ? v0 : 0.2f * v0;  v1 = (v1 > 0.f) ? v1 : 0.2f * v1;
        v2 = (v2 > 0.f) ? v2 : 0.2f * v2;  v3 = (v3 > 0.f) ? v3 : 0.2f * v3;
        u0 = (u0 > 0.f) ? u0 : 0.2f * u0;  u1 = (u1 > 0.f) ? u1 : 0.2f * u1;
        u2 = (u2 > 0.f) ? u2 : 0.2f * u2;  u3 = (u3 > 0.f) ? u3 : 0.2f * u3;
        float p = fmaf(v0, at0.x, fmaf(v1, at0.y, fmaf(v2, at0.z, v3 * at0.w)))
                + fmaf(u0, at1.x, fmaf(u1, at1.y, fmaf(u2, at1.z, u3 * at1.w)));
#pragma unroll
        for (int o = 16; o > 0; o >>= 1)
            p += __shfl_xor_sync(0xffffffffu, p, o);
        float ex = __expf(p);
        den += ex;
        num0.x = fmaf(ex, xl0.x, num0.x); num0.y = fmaf(ex, xl0.y, num0.y);
        num0.z = fmaf(ex, xl0.z, num0.z); num0.w = fmaf(ex, xl0.w, num0.w);
        num1.x = fmaf(ex, xl1.x, num1.x); num1.y = fmaf(ex, xl1.y, num1.y);
        num1.z = fmaf(ex, xl1.z, num1.z); num1.w = fmaf(ex, xl1.w, num1.w);
    }

    const float4 bA = *(const float4*)&bias[cA];
    const float4 bB = *(const float4*)&bias[cB];
    const float inv = 1.f / den;
    float4 rA, rB;
    rA.x = fmaxf(fmaf(num0.x, inv, bA.x), 0.f);
    rA.y = fmaxf(fmaf(num0.y, inv, bA.y), 0.f);
    rA.z = fmaxf(fmaf(num0.z, inv, bA.z), 0.f);
    rA.w = fmaxf(fmaf(num0.w, inv, bA.w), 0.f);
    rB.x = fmaxf(fmaf(num1.x, inv, bB.x), 0.f);
    rB.y = fmaxf(fmaf(num1.y, inv, bB.y), 0.f);
    rB.z = fmaxf(fmaf(num1.z, inv, bB.z), 0.f);
    rB.w = fmaxf(fmaf(num1.w, inv, bB.w), 0.f);
    *(float4*)&out[(size_t)n * CC + cA] = rA;
    *(float4*)&out[(size_t)n * CC + cB] = rB;
}

/* ---------------- launch ---------------- */
extern "C" void kernel_launch(void* const* d_in, const int* in_sizes, int n_in,
                              void* d_out, int out_size)
{
    const float* x    = (const float*)d_in[0];
    const int*   ei   = (const int*)  d_in[1];
    const float* Wl1  = (const float*)d_in[2];
    const float* Wr1  = (const float*)d_in[3];
    const float* att1 = (const float*)d_in[4];
    const float* b1   = (const float*)d_in[5];
    const float* Wl2  = (const float*)d_in[6];
    const float* Wr2  = (const float*)d_in[7];
    const float* att2 = (const float*)d_in[8];
    const float* b2   = (const float*)d_in[9];
    float* out = (float*)d_out;

    __half *p_Ax1, *p_Bt1, *p_Ax2, *p_Bt2;
    float *p_C1, *p_C2;
    cudaGetSymbolAddress((void**)&p_Ax1, g_Ax1);
    cudaGetSymbolAddress((void**)&p_Bt1, g_Bt1);
    cudaGetSymbolAddress((void**)&p_C1,  g_C1);
    cudaGetSymbolAddress((void**)&p_Ax2, g_Ax2);
    cudaGetSymbolAddress((void**)&p_Bt2, g_Bt2);
    cudaGetSymbolAddress((void**)&p_C2,  g_C2);

    cudaFuncSetAttribute(k_gemm_tc, cudaFuncAttributeMaxDynamicSharedMemorySize, GEMM_SMEM);

    /* merged prologue (splits + edge count) + CSR chain */
    k_prep<<<PREP_BLOCKS, 256>>>(x, Wl1, Wr1, Wl2, Wr2, ei);
    k_scan<<<1, 1024>>>();
    k_fill<<<(ET + 255) / 256, 256>>>(ei);

    /* layer 1 */
    k_gemm_tc<<<dim3(NT1 / BN, NN / BM), 256, GEMM_SMEM>>>(p_Ax1, p_Bt1, p_C1, NT1);
    k_fused1<<<NN / 2, 256>>>(att1, b1);

    /* layer 2 */
    k_gemm_tc<<<dim3(NT2 / BN, NN / BM), 256, GEMM_SMEM>>>(p_Ax2, p_Bt2, p_C2, NT2);
    k_fused2<<<NN / 8, 256>>>(att2, b2, out);
}

// round 15
// speedup vs baseline: 1.0274x; 1.0046x over previous
#include <cuda_runtime.h>
#include <cuda_fp16.h>
#include <math.h>
#include <stdint.h>

#define NN   8192
#define EE   98304
#define ET   106496          /* EE + NN self loops */
#define K1   1024            /* inner dim of both GEMMs */
#define CC   256
#define NT1  2048            /* layer-1 combined output cols (xl|xr) */
#define NT2  512             /* layer-2 combined output cols */

/* ---------------- scratch (static device memory, no allocs) ----------------
   fp16 2-term split GEMM: C = Ah*Bh + Ah*Bl.  C stored as fp16 (halves the
   fused-phase read traffic and the GEMM epilogue store traffic).            */
__device__ __half g_Ax1[(size_t)NN * K1];
__device__ __half g_Bt1[(size_t)NT1 * 2 * K1];
__device__ __half g_C1 [(size_t)NN * NT1];
__device__ __half g_Ax2[(size_t)NN * K1];
__device__ __half g_Bt2[(size_t)NT2 * 2 * K1];
__device__ __half g_C2 [(size_t)NN * NT2];
__device__ int   g_counts [NN];     /* zero at entry; scan resets to zero    */
__device__ int   g_offsets[NN + 1];
__device__ int   g_cursor [NN];
__device__ int   g_csr    [ET];     /* src node per CSR slot */

/* ---------------- PTX helpers ---------------- */
__device__ __forceinline__ uint32_t smem_u32(const void* p) {
    uint32_t a;
    asm("{ .reg .u64 t; cvta.to.shared.u64 t, %1; cvt.u32.u64 %0, t; }" : "=r"(a) : "l"(p));
    return a;
}
#define CP16(dst, src) asm volatile("cp.async.cg.shared.global [%0], [%1], 16;" :: "r"(dst), "l"(src) : "memory")
#define CP_COMMIT()    asm volatile("cp.async.commit_group;" ::: "memory")

__device__ __forceinline__ void ldsm4(uint32_t* r, uint32_t addr) {
    asm volatile("ldmatrix.sync.aligned.m8n8.x4.shared.b16 {%0,%1,%2,%3}, [%4];"
        : "=r"(r[0]), "=r"(r[1]), "=r"(r[2]), "=r"(r[3]) : "r"(addr));
}
__device__ __forceinline__ void mma16816(float* c, const uint32_t* a, const uint32_t* b) {
    asm volatile(
        "mma.sync.aligned.m16n8k16.row.col.f32.f16.f16.f32 "
        "{%0,%1,%2,%3}, {%4,%5,%6,%7}, {%8,%9}, {%0,%1,%2,%3};"
        : "+f"(c[0]), "+f"(c[1]), "+f"(c[2]), "+f"(c[3])
        : "r"(a[0]), "r"(a[1]), "r"(a[2]), "r"(a[3]), "r"(b[0]), "r"(b[1]));
}

/* load 4 consecutive halves -> float4 */
__device__ __forceinline__ float4 ldh4(const __half* p) {
    __half2 a = *(const __half2*)p;
    __half2 b = *(const __half2*)(p + 2);
    float2 fa = __half22float2(a), fb = __half22float2(b);
    return make_float4(fa.x, fa.y, fb.x, fb.y);
}

/* ---------------- merged prologue ---------------- */
#define PREP_BLOCKS 11136

__device__ __forceinline__ void split_w_body(
    const float* __restrict__ W, __half* __restrict__ Bt,
    int Nout, int n_off, int local, float* tbuf /* 32x33 smem */)
{
    int nblk = Nout / 32;
    int nx = (local % nblk) * 32;
    int kx = (local / nblk) * 32;
    int tx = threadIdx.x & 31, ty = threadIdx.x >> 5;   /* 32 x 8 */
#pragma unroll
    for (int i = 0; i < 32; i += 8)
        tbuf[(ty + i) * 33 + tx] = W[(size_t)(kx + ty + i) * Nout + nx + tx];
    __syncthreads();
#pragma unroll
    for (int i = 0; i < 32; i += 8) {
        float v = tbuf[tx * 33 + ty + i];
        int n = n_off + nx + ty + i, k = kx + tx;
        __half h = __float2half(v);
        Bt[(size_t)n * 2048 + k]        = h;
        Bt[(size_t)n * 2048 + 1024 + k] = __float2half(v - __half2float(h));
    }
}

__global__ void __launch_bounds__(256)
k_prep(const float* __restrict__ X,
       const float* __restrict__ Wl1, const float* __restrict__ Wr1,
       const float* __restrict__ Wl2, const float* __restrict__ Wr2,
       const int* __restrict__ ei)
{
    __shared__ float tbuf[32 * 33];
    const int b = blockIdx.x;
    if (b < 8192) {
        int idx = b * 256 + threadIdx.x;            /* NN*K1/4 items */
        int r = idx >> 8, kq = idx & 255;
        float4 v = *(const float4*)(X + ((size_t)r << 10) + kq * 4);
        size_t base = (size_t)r * 1024 + kq * 4;
        *(__half2*)&g_Ax1[base]     = __halves2half2(__float2half(v.x), __float2half(v.y));
        *(__half2*)&g_Ax1[base + 2] = __halves2half2(__float2half(v.z), __float2half(v.w));
    } else if (b < 9216) {
        split_w_body(Wl1, g_Bt1, 1024, 0,    b - 8192,  tbuf);
    } else if (b < 10240) {
        split_w_body(Wr1, g_Bt1, 1024, 1024, b - 9216,  tbuf);
    } else if (b < 10496) {
        split_w_body(Wl2, g_Bt2, 256,  0,    b - 10240, tbuf);
    } else if (b < 10752) {
        split_w_body(Wr2, g_Bt2, 256,  256,  b - 10496, tbuf);
    } else {
        int e = (b - 10752) * 256 + threadIdx.x;
        if (e < EE) atomicAdd(&g_counts[ei[EE + e]], 1);
    }
}

/* ---------------- CSR build ---------------- */
__global__ void k_scan() {
    __shared__ int warp_sums[32];
    int t = threadIdx.x, base = t * 8, v[8], s = 0;
#pragma unroll
    for (int i = 0; i < 8; i++) {
        v[i] = g_counts[base + i] + 1;     /* +1 = self loop */
        g_counts[base + i] = 0;            /* reset for next replay */
        s += v[i];
    }
    int lane = t & 31, w = t >> 5, ps = s;
#pragma unroll
    for (int o = 1; o < 32; o <<= 1) {
        int x = __shfl_up_sync(0xffffffffu, ps, o);
        if (lane >= o) ps += x;
    }
    if (lane == 31) warp_sums[w] = ps;
    __syncthreads();
    if (w == 0) {
        int x = warp_sums[lane];
#pragma unroll
        for (int o = 1; o < 32; o <<= 1) {
            int y = __shfl_up_sync(0xffffffffu, x, o);
            if (lane >= o) x += y;
        }
        warp_sums[lane] = x;
    }
    __syncthreads();
    int run = ps - s + (w > 0 ? warp_sums[w - 1] : 0);
#pragma unroll
    for (int i = 0; i < 8; i++) {
        g_offsets[base + i] = run;
        g_cursor [base + i] = run;
        run += v[i];
    }
    if (t == 1023) g_offsets[NN] = run;
}
__global__ void k_fill(const int* __restrict__ ei) {
    int idx = blockIdx.x * blockDim.x + threadIdx.x;
    if (idx >= ET) return;
    int src, dst;
    if (idx < EE) { src = ei[idx]; dst = ei[EE + idx]; }
    else          { src = dst = idx - EE; }
    g_csr[atomicAdd(&g_cursor[dst], 1)] = src;
}

/* ---------------- mma.sync fp16 2-term GEMM (R12 loop; fp16 C epilogue) --- */
#define BM   128
#define BN   128
#define BK   64
#define NST  3
#define NIT  32                  /* 2*K1 / BK */
#define STR  36                  /* u32 stride per row (32 kpairs + 4 pad) */
#define A_U32 (BM * STR)
#define B_U32 (BN * STR)
#define STAGE_BYTES ((A_U32 + B_U32) * 4)
#define GEMM_SMEM (NST * STAGE_BYTES)

__global__ void __launch_bounds__(256, 2)
k_gemm_tc(const __half* __restrict__ A, const __half* __restrict__ B,
          __half* __restrict__ C, int Ntot)
{
    extern __shared__ char smem[];
    const uint32_t sb = smem_u32(smem);
    const int tid = threadIdx.x;
    const int lane = tid & 31;
    const int w = tid >> 5;
    const int wm = (w & 1) * 64;
    const int wn = (w >> 1) * 32;
    const int row0 = blockIdx.y * BM;
    const int col0 = blockIdx.x * BN;
    const int K2 = 2 * K1;

    float acc[4][4][4];
#pragma unroll
    for (int i = 0; i < 4; i++)
#pragma unroll
        for (int j = 0; j < 4; j++)
#pragma unroll
            for (int q = 0; q < 4; q++) acc[i][j][q] = 0.f;

    const int msel = lane >> 3, within = lane & 7;
    const int a_r = (msel & 1) * 8 + within;
    const int a_c = (msel >> 1) * 4;
    const int b_r = (msel >> 1) * 8 + within;
    const int b_c = (msel & 1) * 4;

    auto load_chunk = [&](int ch) {
        int a_k0 = (ch & 15) * BK;      /* A hi reused across both passes */
        int b_k0 = ch * BK;             /* B walks hi then lo             */
        uint32_t sa = sb + (ch % NST) * STAGE_BYTES;
        uint32_t sB = sa + A_U32 * 4;
#pragma unroll
        for (int i = 0; i < 4; i++) {
            int lin = tid + i * 256, r = lin >> 3, j = lin & 7;
            CP16(sa + r * (STR * 4) + j * 16,
                 __cvta_generic_to_global(A + (size_t)(row0 + r) * K1 + a_k0 + j * 8));
        }
#pragma unroll
        for (int i = 0; i < 4; i++) {
            int lin = tid + i * 256, r = lin >> 3, j = lin & 7;
            CP16(sB + r * (STR * 4) + j * 16,
                 __cvta_generic_to_global(B + (size_t)(col0 + r) * K2 + b_k0 + j * 8));
        }
        CP_COMMIT();
    };

    load_chunk(0); load_chunk(1);

    for (int it = 0; it < NIT; it++) {
        if (it < NIT - 1) asm volatile("cp.async.wait_group 1;" ::: "memory");
        else              asm volatile("cp.async.wait_group 0;" ::: "memory");
        __syncthreads();
        if (it + 2 < NIT) load_chunk(it + 2);

        uint32_t sa = sb + (it % NST) * STAGE_BYTES;
        uint32_t sB = sa + A_U32 * 4;
#pragma unroll
        for (int kk = 0; kk < 4; kk++) {
            uint32_t af[4][4], bf[4][2];
#pragma unroll
            for (int mf = 0; mf < 4; mf++)
                ldsm4(af[mf], sa + ((wm + mf * 16 + a_r) * STR + kk * 8 + a_c) * 4);
#pragma unroll
            for (int p = 0; p < 2; p++) {
                uint32_t t4[4];
                ldsm4(t4, sB + ((wn + p * 16 + b_r) * STR + kk * 8 + b_c) * 4);
                bf[2 * p][0] = t4[0]; bf[2 * p][1] = t4[1];
                bf[2 * p + 1][0] = t4[2]; bf[2 * p + 1][1] = t4[3];
            }
#pragma unroll
            for (int mf = 0; mf < 4; mf++)
#pragma unroll
                for (int nf = 0; nf < 4; nf++)
                    mma16816(acc[mf][nf], af[mf], bf[nf]);
        }
    }

    /* fp16 epilogue: half the store bytes */
    const int r = lane >> 2, q = lane & 3;
#pragma unroll
    for (int mf = 0; mf < 4; mf++) {
        int rg = row0 + wm + mf * 16 + r;
#pragma unroll
        for (int nf = 0; nf < 4; nf++) {
            __half* p0 = C + (size_t)rg * Ntot + col0 + wn + nf * 8 + q * 2;
            *(__half2*)p0 = __halves2half2(__float2half(acc[mf][nf][0]), __float2half(acc[mf][nf][1]));
            *(__half2*)(p0 + (size_t)8 * Ntot) =
                __halves2half2(__float2half(acc[mf][nf][2]), __float2half(acc[mf][nf][3]));
        }
    }
}

/* ---------------- fused layer-1: warp per (node, head), fp16 reads -------- */
__global__ void __launch_bounds__(256)
k_fused1(const float* __restrict__ att, const float* __restrict__ bias)
{
    const int w = threadIdx.x >> 5;
    const int lane = threadIdx.x & 31;
    const int n = blockIdx.x * 2 + (w >> 2);
    const int h = w & 3;
    const int cA = h * 256 + lane * 4;
    const int cB = cA + 128;

    const __half* base1 = g_C1;
    const float4 xr0 = ldh4(&base1[(size_t)n * NT1 + 1024 + cA]);
    const float4 xr1 = ldh4(&base1[(size_t)n * NT1 + 1024 + cB]);
    const float4 at0 = *(const float4*)&att[cA];
    const float4 at1 = *(const float4*)&att[cB];

    float4 num0 = make_float4(0.f, 0.f, 0.f, 0.f);
    float4 num1 = make_float4(0.f, 0.f, 0.f, 0.f);
    float den = 0.f;
    const int beg = g_offsets[n], end = g_offsets[n + 1];

    for (int j = beg; j < end; j++) {
        int s = g_csr[j];
        const __half* xl_row = &base1[(size_t)s * NT1];
        float4 xl0 = ldh4(&xl_row[cA]);
        float4 xl1 = ldh4(&xl_row[cB]);
        float v0 = xl0.x + xr0.x, v1 = xl0.y + xr0.y, v2 = xl0.z + xr0.z, v3 = xl0.w + xr0.w;
        float u0 = xl1.x + xr1.x, u1 = xl1.y + xr1.y, u2 = xl1.z + xr1.z, u3 = xl1.w + xr1.w;
        v0 = (v0 > 0.f) ? v0 : 0.2f * v0;  v1 = (v1 > 0.f) ? v1 : 0.2f * v1;
        v2 = (v2 > 0.f) ? v2 : 0.2f * v2;  v3 = (v3 > 0.f) ? v3 : 0.2f * v3;
        u0 = (u0 > 0.f) ? u0 : 0.2f * u0;  u1 = (u1 > 0.f) ? u1 : 0.2f * u1;
        u2 = (u2 > 0.f) ? u2 : 0.2f * u2;  u3 = (u3 > 0.f) ? u3 : 0.2f * u3;
        float p = fmaf(v0, at0.x, fmaf(v1, at0.y, fmaf(v2, at0.z, v3 * at0.w)))
                + fmaf(u0, at1.x, fmaf(u1, at1.y, fmaf(u2, at1.z, u3 * at1.w)));
#pragma unroll
        for (int o = 16; o > 0; o >>= 1)
            p += __shfl_xor_sync(0xffffffffu, p, o);
        float ex = __expf(p);
        den += ex;
        num0.x = fmaf(ex, xl0.x, num0.x); num0.y = fmaf(ex, xl0.y, num0.y);
        num0.z = fmaf(ex, xl0.z, num0.z); num0.w = fmaf(ex, xl0.w, num0.w);
        num1.x = fmaf(ex, xl1.x, num1.x); num1.y = fmaf(ex, xl1.y, num1.y);
        num1.z = fmaf(ex, xl1.z, num1.z); num1.w = fmaf(ex, xl1.w, num1.w);
    }

    const float4 bA = *(const float4*)&bias[cA];
    const float4 bB = *(const float4*)&bias[cB];
    const float inv = 1.f / den;
    float r0 = fmaxf(fmaf(num0.x, inv, bA.x), 0.f);
    float r1 = fmaxf(fmaf(num0.y, inv, bA.y), 0.f);
    float r2 = fmaxf(fmaf(num0.z, inv, bA.z), 0.f);
    float r3 = fmaxf(fmaf(num0.w, inv, bA.w), 0.f);
    float s0 = fmaxf(fmaf(num1.x, inv, bB.x), 0.f);
    float s1 = fmaxf(fmaf(num1.y, inv, bB.y), 0.f);
    float s2 = fmaxf(fmaf(num1.z, inv, bB.z), 0.f);
    float s3 = fmaxf(fmaf(num1.w, inv, bB.w), 0.f);

    /* layer-2 A operand: fp16 hi only */
    size_t baseA = (size_t)n * 1024 + cA;
    size_t baseB = (size_t)n * 1024 + cB;
    *(__half2*)&g_Ax2[baseA]     = __halves2half2(__float2half(r0), __float2half(r1));
    *(__half2*)&g_Ax2[baseA + 2] = __halves2half2(__float2half(r2), __float2half(r3));
    *(__half2*)&g_Ax2[baseB]     = __halves2half2(__float2half(s0), __float2half(s1));
    *(__half2*)&g_Ax2[baseB + 2] = __halves2half2(__float2half(s2), __float2half(s3));
}

/* ---------------- fused layer-2: warp per node, fp16 reads ---------------- */
__global__ void __launch_bounds__(256)
k_fused2(const float* __restrict__ att, const float* __restrict__ bias,
         float* __restrict__ out)
{
    const int w = threadIdx.x >> 5;
    const int lane = threadIdx.x & 31;
    const int n = blockIdx.x * 8 + w;
    const int cA = lane * 4;
    const int cB = cA + 128;

    const __half* base2 = g_C2;
    const float4 xr0 = ldh4(&base2[(size_t)n * NT2 + 256 + cA]);
    const float4 xr1 = ldh4(&base2[(size_t)n * NT2 + 256 + cB]);
    const float4 at0 = *(const float4*)&att[cA];
    const float4 at1 = *(const float4*)&att[cB];

    float4 num0 = make_float4(0.f, 0.f, 0.f, 0.f);
    float4 num1 = make_float4(0.f, 0.f, 0.f, 0.f);
    float den = 0.f;
    const int beg = g_offsets[n], end = g_offsets[n + 1];

    for (int j = beg; j < end; j++) {
        int s = g_csr[j];
        const __half* xl_row = &base2[(size_t)s * NT2];
        float4 xl0 = ldh4(&xl_row[cA]);
        float4 xl1 = ldh4(&xl_row[cB]);
        float v0 = xl0.x + xr0.x, v1 = xl0.y + xr0.y, v2 = xl0.z + xr0.z, v3 = xl0.w + xr0.w;
        float u0 = xl1.x + xr1.x, u1 = xl1.y + xr1.y, u2 = xl1.z + xr1.z, u3 = xl1.w + xr1.w;
        v0 = (v0 > 0.f) ? v0 : 0.2f * v0;  v1 = (v1 > 0.f) ? v1 : 0.2f * v1;
        v2 = (v2 > 0.f) ? v2 : 0.2f * v2;  v3 = (v3 > 0.f) ? v3 : 0.2f * v3;
        u0 = (u0 > 0.f) ? u0 : 0.2f * u0;  u1 = (u1 > 0.f) ? u1 : 0.2f * u1;
        u2 = (u2 > 0.f) ? u2 : 0.2f * u2;  u3 = (u3 > 0.f) ? u3 : 0.2f * u3;
        float p = fmaf(v0, at0.x, fmaf(v1, at0.y, fmaf(v2, at0.z, v3 * at0.w)))
                + fmaf(u0, at1.x, fmaf(u1, at1.y, fmaf(u2, at1.z, u3 * at1.w)));
#pragma unroll
        for (int o = 16; o > 0; o >>= 1)
            p += __shfl_xor_sync(0xffffffffu, p, o);
        float ex = __expf(p);
        den += ex;
        num0.x = fmaf(ex, xl0.x, num0.x); num0.y = fmaf(ex, xl0.y, num0.y);
        num0.z = fmaf(ex, xl0.z, num0.z); num0.w = fmaf(ex, xl0.w, num0.w);
        num1.x = fmaf(ex, xl1.x, num1.x); num1.y = fmaf(ex, xl1.y, num1.y);
        num1.z = fmaf(ex, xl1.z, num1.z); num1.w = fmaf(ex, xl1.w, num1.w);
    }

    const float4 bA = *(const float4*)&bias[cA];
    const float4 bB = *(const float4*)&bias[cB];
    const float inv = 1.f / den;
    float4 rA, rB;
    rA.x = fmaxf(fmaf(num0.x, inv, bA.x), 0.f);
    rA.y = fmaxf(fmaf(num0.y, inv, bA.y), 0.f);
    rA.z = fmaxf(fmaf(num0.z, inv, bA.z), 0.f);
    rA.w = fmaxf(fmaf(num0.w, inv, bA.w), 0.f);
    rB.x = fmaxf(fmaf(num1.x, inv, bB.x), 0.f);
    rB.y = fmaxf(fmaf(num1.y, inv, bB.y), 0.f);
    rB.z = fmaxf(fmaf(num1.z, inv, bB.z), 0.f);
    rB.w = fmaxf(fmaf(num1.w, inv, bB.w), 0.f);
    *(float4*)&out[(size_t)n * CC + cA] = rA;
    *(float4*)&out[(size_t)n * CC + cB] = rB;
}

/* ---------------- launch ---------------- */
extern "C" void kernel_launch(void* const* d_in, const int* in_sizes, int n_in,
                              void* d_out, int out_size)
{
    const float* x    = (const float*)d_in[0];
    const int*   ei   = (const int*)  d_in[1];
    const float* Wl1  = (const float*)d_in[2];
    const float* Wr1  = (const float*)d_in[3];
    const float* att1 = (const float*)d_in[4];
    const float* b1   = (const float*)d_in[5];
    const float* Wl2  = (const float*)d_in[6];
    const float* Wr2  = (const float*)d_in[7];
    const float* att2 = (const float*)d_in[8];
    const float* b2   = (const float*)d_in[9];
    float* out = (float*)d_out;

    __half *p_Ax1, *p_Bt1, *p_Ax2, *p_Bt2, *p_C1, *p_C2;
    cudaGetSymbolAddress((void**)&p_Ax1, g_Ax1);
    cudaGetSymbolAddress((void**)&p_Bt1, g_Bt1);
    cudaGetSymbolAddress((void**)&p_C1,  g_C1);
    cudaGetSymbolAddress((void**)&p_Ax2, g_Ax2);
    cudaGetSymbolAddress((void**)&p_Bt2, g_Bt2);
    cudaGetSymbolAddress((void**)&p_C2,  g_C2);

    cudaFuncSetAttribute(k_gemm_tc, cudaFuncAttributeMaxDynamicSharedMemorySize, GEMM_SMEM);

    /* merged prologue (splits + edge count) + CSR chain */
    k_prep<<<PREP_BLOCKS, 256>>>(x, Wl1, Wr1, Wl2, Wr2, ei);
    k_scan<<<1, 1024>>>();
    k_fill<<<(ET + 255) / 256, 256>>>(ei);

    /* layer 1 */
    k_gemm_tc<<<dim3(NT1 / BN, NN / BM), 256, GEMM_SMEM>>>(p_Ax1, p_Bt1, p_C1, NT1);
    k_fused1<<<NN / 2, 256>>>(att1, b1);

    /* layer 2 */
    k_gemm_tc<<<dim3(NT2 / BN, NN / BM), 256, GEMM_SMEM>>>(p_Ax2, p_Bt2, p_C2, NT2);
    k_fused2<<<NN / 8, 256>>>(att2, b2, out);
}

// round 16
// speedup vs baseline: 1.5531x; 1.5117x over previous
#include <cuda_runtime.h>
#include <cuda_fp16.h>
#include <math.h>
#include <stdint.h>

#define NN   8192
#define EE   98304
#define ET   106496          /* EE + NN self loops */
#define K1   1024            /* inner dim of both GEMMs */
#define CC   256
#define NT1  2048            /* layer-1 combined output cols (xl|xr) */
#define NT2  512             /* layer-2 combined output cols */

/* ---------------- scratch (static device memory, no allocs) ----------------
   pure fp16 GEMM: C = Ah*Bh (A and B rounded to fp16, fp32 accumulate).    */
__device__ __half g_Ax1[(size_t)NN * K1];
__device__ __half g_Bt1[(size_t)NT1 * K1];
__device__ __half g_C1 [(size_t)NN * NT1];
__device__ __half g_Ax2[(size_t)NN * K1];
__device__ __half g_Bt2[(size_t)NT2 * K1];
__device__ __half g_C2 [(size_t)NN * NT2];
__device__ int   g_counts [NN];     /* zero at entry; scan resets to zero    */
__device__ int   g_offsets[NN + 1];
__device__ int   g_cursor [NN];
__device__ int   g_csr    [ET];     /* src node per CSR slot */

/* ---------------- PTX helpers ---------------- */
__device__ __forceinline__ uint32_t smem_u32(const void* p) {
    uint32_t a;
    asm("{ .reg .u64 t; cvta.to.shared.u64 t, %1; cvt.u32.u64 %0, t; }" : "=r"(a) : "l"(p));
    return a;
}
#define CP16(dst, src) asm volatile("cp.async.cg.shared.global [%0], [%1], 16;" :: "r"(dst), "l"(src) : "memory")
#define CP_COMMIT()    asm volatile("cp.async.commit_group;" ::: "memory")

__device__ __forceinline__ void ldsm4(uint32_t* r, uint32_t addr) {
    asm volatile("ldmatrix.sync.aligned.m8n8.x4.shared.b16 {%0,%1,%2,%3}, [%4];"
        : "=r"(r[0]), "=r"(r[1]), "=r"(r[2]), "=r"(r[3]) : "r"(addr));
}
__device__ __forceinline__ void mma16816(float* c, const uint32_t* a, const uint32_t* b) {
    asm volatile(
        "mma.sync.aligned.m16n8k16.row.col.f32.f16.f16.f32 "
        "{%0,%1,%2,%3}, {%4,%5,%6,%7}, {%8,%9}, {%0,%1,%2,%3};"
        : "+f"(c[0]), "+f"(c[1]), "+f"(c[2]), "+f"(c[3])
        : "r"(a[0]), "r"(a[1]), "r"(a[2]), "r"(a[3]), "r"(b[0]), "r"(b[1]));
}

/* load 4 consecutive halves -> float4 */
__device__ __forceinline__ float4 ldh4(const __half* p) {
    __half2 a = *(const __half2*)p;
    __half2 b = *(const __half2*)(p + 2);
    float2 fa = __half22float2(a), fb = __half22float2(b);
    return make_float4(fa.x, fa.y, fb.x, fb.y);
}

/* ---------------- merged prologue ---------------- */
#define PREP_BLOCKS 11136

__device__ __forceinline__ void split_w_body(
    const float* __restrict__ W, __half* __restrict__ Bt,
    int Nout, int n_off, int local, float* tbuf /* 32x33 smem */)
{
    int nblk = Nout / 32;
    int nx = (local % nblk) * 32;
    int kx = (local / nblk) * 32;
    int tx = threadIdx.x & 31, ty = threadIdx.x >> 5;   /* 32 x 8 */
#pragma unroll
    for (int i = 0; i < 32; i += 8)
        tbuf[(ty + i) * 33 + tx] = W[(size_t)(kx + ty + i) * Nout + nx + tx];
    __syncthreads();
#pragma unroll
    for (int i = 0; i < 32; i += 8) {
        float v = tbuf[tx * 33 + ty + i];
        int n = n_off + nx + ty + i, k = kx + tx;
        Bt[(size_t)n * K1 + k] = __float2half(v);
    }
}

__global__ void __launch_bounds__(256)
k_prep(const float* __restrict__ X,
       const float* __restrict__ Wl1, const float* __restrict__ Wr1,
       const float* __restrict__ Wl2, const float* __restrict__ Wr2,
       const int* __restrict__ ei)
{
    __shared__ float tbuf[32 * 33];
    const int b = blockIdx.x;
    if (b < 8192) {
        int idx = b * 256 + threadIdx.x;            /* NN*K1/4 items */
        int r = idx >> 8, kq = idx & 255;
        float4 v = *(const float4*)(X + ((size_t)r << 10) + kq * 4);
        size_t base = (size_t)r * 1024 + kq * 4;
        *(__half2*)&g_Ax1[base]     = __halves2half2(__float2half(v.x), __float2half(v.y));
        *(__half2*)&g_Ax1[base + 2] = __halves2half2(__float2half(v.z), __float2half(v.w));
    } else if (b < 9216) {
        split_w_body(Wl1, g_Bt1, 1024, 0,    b - 8192,  tbuf);
    } else if (b < 10240) {
        split_w_body(Wr1, g_Bt1, 1024, 1024, b - 9216,  tbuf);
    } else if (b < 10496) {
        split_w_body(Wl2, g_Bt2, 256,  0,    b - 10240, tbuf);
    } else if (b < 10752) {
        split_w_body(Wr2, g_Bt2, 256,  256,  b - 10496, tbuf);
    } else {
        int e = (b - 10752) * 256 + threadIdx.x;
        if (e < EE) atomicAdd(&g_counts[ei[EE + e]], 1);
    }
}

/* ---------------- CSR build ---------------- */
__global__ void k_scan() {
    __shared__ int warp_sums[32];
    int t = threadIdx.x, base = t * 8, v[8], s = 0;
#pragma unroll
    for (int i = 0; i < 8; i++) {
        v[i] = g_counts[base + i] + 1;     /* +1 = self loop */
        g_counts[base + i] = 0;            /* reset for next replay */
        s += v[i];
    }
    int lane = t & 31, w = t >> 5, ps = s;
#pragma unroll
    for (int o = 1; o < 32; o <<= 1) {
        int x = __shfl_up_sync(0xffffffffu, ps, o);
        if (lane >= o) ps += x;
    }
    if (lane == 31) warp_sums[w] = ps;
    __syncthreads();
    if (w == 0) {
        int x = warp_sums[lane];
#pragma unroll
        for (int o = 1; o < 32; o <<= 1) {
            int y = __shfl_up_sync(0xffffffffu, x, o);
            if (lane >= o) x += y;
        }
        warp_sums[lane] = x;
    }
    __syncthreads();
    int run = ps - s + (w > 0 ? warp_sums[w - 1] : 0);
#pragma unroll
    for (int i = 0; i < 8; i++) {
        g_offsets[base + i] = run;
        g_cursor [base + i] = run;
        run += v[i];
    }
    if (t == 1023) g_offsets[NN] = run;
}
__global__ void k_fill(const int* __restrict__ ei) {
    int idx = blockIdx.x * blockDim.x + threadIdx.x;
    if (idx >= ET) return;
    int src, dst;
    if (idx < EE) { src = ei[idx]; dst = ei[EE + idx]; }
    else          { src = dst = idx - EE; }
    g_csr[atomicAdd(&g_cursor[dst], 1)] = src;
}

/* ---------------- mma.sync pure-fp16 GEMM (K = K1) -----------------------
   CTA 128x128, warps 64x32, BK=64, NST=3, one sync per chunk, NIT=16.    */
#define BM   128
#define BN   128
#define BK   64
#define NST  3
#define NIT  16                  /* K1 / BK */
#define STR  36                  /* u32 stride per row (32 kpairs + 4 pad) */
#define A_U32 (BM * STR)
#define B_U32 (BN * STR)
#define STAGE_BYTES ((A_U32 + B_U32) * 4)
#define GEMM_SMEM (NST * STAGE_BYTES)

__global__ void __launch_bounds__(256, 2)
k_gemm_tc(const __half* __restrict__ A, const __half* __restrict__ B,
          __half* __restrict__ C, int Ntot)
{
    extern __shared__ char smem[];
    const uint32_t sb = smem_u32(smem);
    const int tid = threadIdx.x;
    const int lane = tid & 31;
    const int w = tid >> 5;
    const int wm = (w & 1) * 64;
    const int wn = (w >> 1) * 32;
    const int row0 = blockIdx.y * BM;
    const int col0 = blockIdx.x * BN;

    float acc[4][4][4];
#pragma unroll
    for (int i = 0; i < 4; i++)
#pragma unroll
        for (int j = 0; j < 4; j++)
#pragma unroll
            for (int q = 0; q < 4; q++) acc[i][j][q] = 0.f;

    const int msel = lane >> 3, within = lane & 7;
    const int a_r = (msel & 1) * 8 + within;
    const int a_c = (msel >> 1) * 4;
    const int b_r = (msel >> 1) * 8 + within;
    const int b_c = (msel & 1) * 4;

    auto load_chunk = [&](int ch) {
        int k0 = ch * BK;
        uint32_t sa = sb + (ch % NST) * STAGE_BYTES;
        uint32_t sB = sa + A_U32 * 4;
#pragma unroll
        for (int i = 0; i < 4; i++) {
            int lin = tid + i * 256, r = lin >> 3, j = lin & 7;
            CP16(sa + r * (STR * 4) + j * 16,
                 __cvta_generic_to_global(A + (size_t)(row0 + r) * K1 + k0 + j * 8));
        }
#pragma unroll
        for (int i = 0; i < 4; i++) {
            int lin = tid + i * 256, r = lin >> 3, j = lin & 7;
            CP16(sB + r * (STR * 4) + j * 16,
                 __cvta_generic_to_global(B + (size_t)(col0 + r) * K1 + k0 + j * 8));
        }
        CP_COMMIT();
    };

    load_chunk(0); load_chunk(1);

    for (int it = 0; it < NIT; it++) {
        if (it < NIT - 1) asm volatile("cp.async.wait_group 1;" ::: "memory");
        else              asm volatile("cp.async.wait_group 0;" ::: "memory");
        __syncthreads();
        if (it + 2 < NIT) load_chunk(it + 2);

        uint32_t sa = sb + (it % NST) * STAGE_BYTES;
        uint32_t sB = sa + A_U32 * 4;
#pragma unroll
        for (int kk = 0; kk < 4; kk++) {
            uint32_t af[4][4], bf[4][2];
#pragma unroll
            for (int mf = 0; mf < 4; mf++)
                ldsm4(af[mf], sa + ((wm + mf * 16 + a_r) * STR + kk * 8 + a_c) * 4);
#pragma unroll
            for (int p = 0; p < 2; p++) {
                uint32_t t4[4];
                ldsm4(t4, sB + ((wn + p * 16 + b_r) * STR + kk * 8 + b_c) * 4);
                bf[2 * p][0] = t4[0]; bf[2 * p][1] = t4[1];
                bf[2 * p + 1][0] = t4[2]; bf[2 * p + 1][1] = t4[3];
            }
#pragma unroll
            for (int mf = 0; mf < 4; mf++)
#pragma unroll
                for (int nf = 0; nf < 4; nf++)
                    mma16816(acc[mf][nf], af[mf], bf[nf]);
        }
    }

    /* fp16 epilogue */
    const int r = lane >> 2, q = lane & 3;
#pragma unroll
    for (int mf = 0; mf < 4; mf++) {
        int rg = row0 + wm + mf * 16 + r;
#pragma unroll
        for (int nf = 0; nf < 4; nf++) {
            __half* p0 = C + (size_t)rg * Ntot + col0 + wn + nf * 8 + q * 2;
            *(__half2*)p0 = __halves2half2(__float2half(acc[mf][nf][0]), __float2half(acc[mf][nf][1]));
            *(__half2*)(p0 + (size_t)8 * Ntot) =
                __halves2half2(__float2half(acc[mf][nf][2]), __float2half(acc[mf][nf][3]));
        }
    }
}

/* ---------------- fused layer-1: warp per (node, head), fp16 reads -------- */
__global__ void __launch_bounds__(256)
k_fused1(const float* __restrict__ att, const float* __restrict__ bias)
{
    const int w = threadIdx.x >> 5;
    const int lane = threadIdx.x & 31;
    const int n = blockIdx.x * 2 + (w >> 2);
    const int h = w & 3;
    const int cA = h * 256 + lane * 4;
    const int cB = cA + 128;

    const __half* base1 = g_C1;
    const float4 xr0 = ldh4(&base1[(size_t)n * NT1 + 1024 + cA]);
    const float4 xr1 = ldh4(&base1[(size_t)n * NT1 + 1024 + cB]);
    const float4 at0 = *(const float4*)&att[cA];
    const float4 at1 = *(const float4*)&att[cB];

    float4 num0 = make_float4(0.f, 0.f, 0.f, 0.f);
    float4 num1 = make_float4(0.f, 0.f, 0.f, 0.f);
    float den = 0.f;
    const int beg = g_offsets[n], end = g_offsets[n + 1];

    for (int j = beg; j < end; j++) {
        int s = g_csr[j];
        const __half* xl_row = &base1[(size_t)s * NT1];
        float4 xl0 = ldh4(&xl_row[cA]);
        float4 xl1 = ldh4(&xl_row[cB]);
        float v0 = xl0.x + xr0.x, v1 = xl0.y + xr0.y, v2 = xl0.z + xr0.z, v3 = xl0.w + xr0.w;
        float u0 = xl1.x + xr1.x, u1 = xl1.y + xr1.y, u2 = xl1.z + xr1.z, u3 = xl1.w + xr1.w;
        v0 = (v0 > 0.f) ? v0 : 0.2f * v0;  v1 = (v1 > 0.f) ? v1 : 0.2f * v1;
        v2 = (v2 > 0.f) ? v2 : 0.2f * v2;  v3 = (v3 > 0.f) ? v3 : 0.2f * v3;
        u0 = (u0 > 0.f) ? u0 : 0.2f * u0;  u1 = (u1 > 0.f) ? u1 : 0.2f * u1;
        u2 = (u2 > 0.f) ? u2 : 0.2f * u2;  u3 = (u3 > 0.f) ? u3 : 0.2f * u3;
        float p = fmaf(v0, at0.x, fmaf(v1, at0.y, fmaf(v2, at0.z, v3 * at0.w)))
                + fmaf(u0, at1.x, fmaf(u1, at1.y, fmaf(u2, at1.z, u3 * at1.w)));
#pragma unroll
        for (int o = 16; o > 0; o >>= 1)
            p += __shfl_xor_sync(0xffffffffu, p, o);
        float ex = __expf(p);
        den += ex;
        num0.x = fmaf(ex, xl0.x, num0.x); num0.y = fmaf(ex, xl0.y, num0.y);
        num0.z = fmaf(ex, xl0.z, num0.z); num0.w = fmaf(ex, xl0.w, num0.w);
        num1.x = fmaf(ex, xl1.x, num1.x); num1.y = fmaf(ex, xl1.y, num1.y);
        num1.z = fmaf(ex, xl1.z, num1.z); num1.w = fmaf(ex, xl1.w, num1.w);
    }

    const float4 bA = *(const float4*)&bias[cA];
    const float4 bB = *(const float4*)&bias[cB];
    const float inv = 1.f / den;
    float r0 = fmaxf(fmaf(num0.x, inv, bA.x), 0.f);
    float r1 = fmaxf(fmaf(num0.y, inv, bA.y), 0.f);
    float r2 = fmaxf(fmaf(num0.z, inv, bA.z), 0.f);
    float r3 = fmaxf(fmaf(num0.w, inv, bA.w), 0.f);
    float s0 = fmaxf(fmaf(num1.x, inv, bB.x), 0.f);
    float s1 = fmaxf(fmaf(num1.y, inv, bB.y), 0.f);
    float s2 = fmaxf(fmaf(num1.z, inv, bB.z), 0.f);
    float s3 = fmaxf(fmaf(num1.w, inv, bB.w), 0.f);

    size_t baseA = (size_t)n * 1024 + cA;
    size_t baseB = (size_t)n * 1024 + cB;
    *(__half2*)&g_Ax2[baseA]     = __halves2half2(__float2half(r0), __float2half(r1));
    *(__half2*)&g_Ax2[baseA + 2] = __halves2half2(__float2half(r2), __float2half(r3));
    *(__half2*)&g_Ax2[baseB]     = __halves2half2(__float2half(s0), __float2half(s1));
    *(__half2*)&g_Ax2[baseB + 2] = __halves2half2(__float2half(s2), __float2half(s3));
}

/* ---------------- fused layer-2: warp per node, fp16 reads ---------------- */
__global__ void __launch_bounds__(256)
k_fused2(const float* __restrict__ att, const float* __restrict__ bias,
         float* __restrict__ out)
{
    const int w = threadIdx.x >> 5;
    const int lane = threadIdx.x & 31;
    const int n = blockIdx.x * 8 + w;
    const int cA = lane * 4;
    const int cB = cA + 128;

    const __half* base2 = g_C2;
    const float4 xr0 = ldh4(&base2[(size_t)n * NT2 + 256 + cA]);
    const float4 xr1 = ldh4(&base2[(size_t)n * NT2 + 256 + cB]);
    const float4 at0 = *(const float4*)&att[cA];
    const float4 at1 = *(const float4*)&att[cB];

    float4 num0 = make_float4(0.f, 0.f, 0.f, 0.f);
    float4 num1 = make_float4(0.f, 0.f, 0.f, 0.f);
    float den = 0.f;
    const int beg = g_offsets[n], end = g_offsets[n + 1];

    for (int j = beg; j < end; j++) {
        int s = g_csr[j];
        const __half* xl_row = &base2[(size_t)s * NT2];
        float4 xl0 = ldh4(&xl_row[cA]);
        float4 xl1 = ldh4(&xl_row[cB]);
        float v0 = xl0.x + xr0.x, v1 = xl0.y + xr0.y, v2 = xl0.z + xr0.z, v3 = xl0.w + xr0.w;
        float u0 = xl1.x + xr1.x, u1 = xl1.y + xr1.y, u2 = xl1.z + xr1.z, u3 = xl1.w + xr1.w;
        v0 = (v0 > 0.f) ? v0 : 0.2f * v0;  v1 = (v1 > 0.f) ? v1 : 0.2f * v1;
        v2 = (v2 > 0.f) ? v2 : 0.2f * v2;  v3 = (v3 > 0.f) ? v3 : 0.2f * v3;
        u0 = (u0 > 0.f) ? u0 : 0.2f * u0;  u1 = (u1 > 0.f) ? u1 : 0.2f * u1;
        u2 = (u2 > 0.f) ? u2 : 0.2f * u2;  u3 = (u3 > 0.f) ? u3 : 0.2f * u3;
        float p = fmaf(v0, at0.x, fmaf(v1, at0.y, fmaf(v2, at0.z, v3 * at0.w)))
                + fmaf(u0, at1.x, fmaf(u1, at1.y, fmaf(u2, at1.z, u3 * at1.w)));
#pragma unroll
        for (int o = 16; o > 0; o >>= 1)
            p += __shfl_xor_sync(0xffffffffu, p, o);
        float ex = __expf(p);
        den += ex;
        num0.x = fmaf(ex, xl0.x, num0.x); num0.y = fmaf(ex, xl0.y, num0.y);
        num0.z = fmaf(ex, xl0.z, num0.z); num0.w = fmaf(ex, xl0.w, num0.w);
        num1.x = fmaf(ex, xl1.x, num1.x); num1.y = fmaf(ex, xl1.y, num1.y);
        num1.z = fmaf(ex, xl1.z, num1.z); num1.w = fmaf(ex, xl1.w, num1.w);
    }

    const float4 bA = *(const float4*)&bias[cA];
    const float4 bB = *(const float4*)&bias[cB];
    const float inv = 1.f / den;
    float4 rA, rB;
    rA.x = fmaxf(fmaf(num0.x, inv, bA.x), 0.f);
    rA.y = fmaxf(fmaf(num0.y, inv, bA.y), 0.f);
    rA.z = fmaxf(fmaf(num0.z, inv, bA.z), 0.f);
    rA.w = fmaxf(fmaf(num0.w, inv, bA.w), 0.f);
    rB.x = fmaxf(fmaf(num1.x, inv, bB.x), 0.f);
    rB.y = fmaxf(fmaf(num1.y, inv, bB.y), 0.f);
    rB.z = fmaxf(fmaf(num1.z, inv, bB.z), 0.f);
    rB.w = fmaxf(fmaf(num1.w, inv, bB.w), 0.f);
    *(float4*)&out[(size_t)n * CC + cA] = rA;
    *(float4*)&out[(size_t)n * CC + cB] = rB;
}

/* ---------------- launch ---------------- */
extern "C" void kernel_launch(void* const* d_in, const int* in_sizes, int n_in,
                              void* d_out, int out_size)
{
    const float* x    = (const float*)d_in[0];
    const int*   ei   = (const int*)  d_in[1];
    const float* Wl1  = (const float*)d_in[2];
    const float* Wr1  = (const float*)d_in[3];
    const float* att1 = (const float*)d_in[4];
    const float* b1   = (const float*)d_in[5];
    const float* Wl2  = (const float*)d_in[6];
    const float* Wr2  = (const float*)d_in[7];
    const float* att2 = (const float*)d_in[8];
    const float* b2   = (const float*)d_in[9];
    float* out = (float*)d_out;

    __half *p_Ax1, *p_Bt1, *p_Ax2, *p_Bt2, *p_C1, *p_C2;
    cudaGetSymbolAddress((void**)&p_Ax1, g_Ax1);
    cudaGetSymbolAddress((void**)&p_Bt1, g_Bt1);
    cudaGetSymbolAddress((void**)&p_C1,  g_C1);
    cudaGetSymbolAddress((void**)&p_Ax2, g_Ax2);
    cudaGetSymbolAddress((void**)&p_Bt2, g_Bt2);
    cudaGetSymbolAddress((void**)&p_C2,  g_C2);

    cudaFuncSetAttribute(k_gemm_tc, cudaFuncAttributeMaxDynamicSharedMemorySize, GEMM_SMEM);

    /* merged prologue (splits + edge count) + CSR chain */
    k_prep<<<PREP_BLOCKS, 256>>>(x, Wl1, Wr1, Wl2, Wr2, ei);
    k_scan<<<1, 1024>>>();
    k_fill<<<(ET + 255) / 256, 256>>>(ei);

    /* layer 1 */
    k_gemm_tc<<<dim3(NT1 / BN, NN / BM), 256, GEMM_SMEM>>>(p_Ax1, p_Bt1, p_C1, NT1);
    k_fused1<<<NN / 2, 256>>>(att1, b1);

    /* layer 2 */
    k_gemm_tc<<<dim3(NT2 / BN, NN / BM), 256, GEMM_SMEM>>>(p_Ax2, p_Bt2, p_C2, NT2);
    k_fused2<<<NN / 8, 256>>>(att2, b2, out);
}

// round 17
// speedup vs baseline: 1.5798x; 1.0172x over previous
#include <cuda_runtime.h>
#include <cuda_fp16.h>
#include <math.h>
#include <stdint.h>

#define NN   8192
#define EE   98304
#define ET   106496          /* EE + NN self loops */
#define K1   1024            /* inner dim of both GEMMs */
#define CC   256
#define NT1  2048            /* layer-1 combined output cols (xl|xr) */
#define NT2  512             /* layer-2 combined output cols */

/* ---------------- scratch (static device memory, no allocs) ----------------
   pure fp16 GEMM: C = Ah*Bh (A and B rounded to fp16, fp32 accumulate).    */
__device__ __half g_Ax1[(size_t)NN * K1];
__device__ __half g_Bt1[(size_t)NT1 * K1];
__device__ __half g_C1 [(size_t)NN * NT1];
__device__ __half g_Ax2[(size_t)NN * K1];
__device__ __half g_Bt2[(size_t)NT2 * K1];
__device__ __half g_C2 [(size_t)NN * NT2];
__device__ int   g_counts [NN];     /* zero at entry; scan resets to zero    */
__device__ int   g_offsets[NN + 1];
__device__ int   g_cursor [NN];
__device__ int   g_csr    [ET];     /* src node per CSR slot */

/* ---------------- PTX helpers ---------------- */
__device__ __forceinline__ uint32_t smem_u32(const void* p) {
    uint32_t a;
    asm("{ .reg .u64 t; cvta.to.shared.u64 t, %1; cvt.u32.u64 %0, t; }" : "=r"(a) : "l"(p));
    return a;
}
#define CP16(dst, src) asm volatile("cp.async.cg.shared.global [%0], [%1], 16;" :: "r"(dst), "l"(src) : "memory")
#define CP_COMMIT()    asm volatile("cp.async.commit_group;" ::: "memory")

__device__ __forceinline__ void ldsm4(uint32_t* r, uint32_t addr) {
    asm volatile("ldmatrix.sync.aligned.m8n8.x4.shared.b16 {%0,%1,%2,%3}, [%4];"
        : "=r"(r[0]), "=r"(r[1]), "=r"(r[2]), "=r"(r[3]) : "r"(addr));
}
__device__ __forceinline__ void mma16816(float* c, const uint32_t* a, const uint32_t* b) {
    asm volatile(
        "mma.sync.aligned.m16n8k16.row.col.f32.f16.f16.f32 "
        "{%0,%1,%2,%3}, {%4,%5,%6,%7}, {%8,%9}, {%0,%1,%2,%3};"
        : "+f"(c[0]), "+f"(c[1]), "+f"(c[2]), "+f"(c[3])
        : "r"(a[0]), "r"(a[1]), "r"(a[2]), "r"(a[3]), "r"(b[0]), "r"(b[1]));
}

/* load 4 consecutive halves -> float4 */
__device__ __forceinline__ float4 ldh4(const __half* p) {
    __half2 a = *(const __half2*)p;
    __half2 b = *(const __half2*)(p + 2);
    float2 fa = __half22float2(a), fb = __half22float2(b);
    return make_float4(fa.x, fa.y, fb.x, fb.y);
}
__device__ __forceinline__ float lrelu(float v) { return (v > 0.f) ? v : 0.2f * v; }

/* ---------------- merged prologue ---------------- */
#define PREP_BLOCKS 11136

__device__ __forceinline__ void split_w_body(
    const float* __restrict__ W, __half* __restrict__ Bt,
    int Nout, int n_off, int local, float* tbuf /* 32x33 smem */)
{
    int nblk = Nout / 32;
    int nx = (local % nblk) * 32;
    int kx = (local / nblk) * 32;
    int tx = threadIdx.x & 31, ty = threadIdx.x >> 5;   /* 32 x 8 */
#pragma unroll
    for (int i = 0; i < 32; i += 8)
        tbuf[(ty + i) * 33 + tx] = W[(size_t)(kx + ty + i) * Nout + nx + tx];
    __syncthreads();
#pragma unroll
    for (int i = 0; i < 32; i += 8) {
        float v = tbuf[tx * 33 + ty + i];
        int n = n_off + nx + ty + i, k = kx + tx;
        Bt[(size_t)n * K1 + k] = __float2half(v);
    }
}

__global__ void __launch_bounds__(256)
k_prep(const float* __restrict__ X,
       const float* __restrict__ Wl1, const float* __restrict__ Wr1,
       const float* __restrict__ Wl2, const float* __restrict__ Wr2,
       const int* __restrict__ ei)
{
    __shared__ float tbuf[32 * 33];
    const int b = blockIdx.x;
    if (b < 8192) {
        int idx = b * 256 + threadIdx.x;            /* NN*K1/4 items */
        int r = idx >> 8, kq = idx & 255;
        float4 v = *(const float4*)(X + ((size_t)r << 10) + kq * 4);
        size_t base = (size_t)r * 1024 + kq * 4;
        *(__half2*)&g_Ax1[base]     = __halves2half2(__float2half(v.x), __float2half(v.y));
        *(__half2*)&g_Ax1[base + 2] = __halves2half2(__float2half(v.z), __float2half(v.w));
    } else if (b < 9216) {
        split_w_body(Wl1, g_Bt1, 1024, 0,    b - 8192,  tbuf);
    } else if (b < 10240) {
        split_w_body(Wr1, g_Bt1, 1024, 1024, b - 9216,  tbuf);
    } else if (b < 10496) {
        split_w_body(Wl2, g_Bt2, 256,  0,    b - 10240, tbuf);
    } else if (b < 10752) {
        split_w_body(Wr2, g_Bt2, 256,  256,  b - 10496, tbuf);
    } else {
        int e = (b - 10752) * 256 + threadIdx.x;
        if (e < EE) atomicAdd(&g_counts[ei[EE + e]], 1);
    }
}

/* ---------------- CSR build ---------------- */
__global__ void k_scan() {
    __shared__ int warp_sums[32];
    int t = threadIdx.x, base = t * 8, v[8], s = 0;
#pragma unroll
    for (int i = 0; i < 8; i++) {
        v[i] = g_counts[base + i] + 1;     /* +1 = self loop */
        g_counts[base + i] = 0;            /* reset for next replay */
        s += v[i];
    }
    int lane = t & 31, w = t >> 5, ps = s;
#pragma unroll
    for (int o = 1; o < 32; o <<= 1) {
        int x = __shfl_up_sync(0xffffffffu, ps, o);
        if (lane >= o) ps += x;
    }
    if (lane == 31) warp_sums[w] = ps;
    __syncthreads();
    if (w == 0) {
        int x = warp_sums[lane];
#pragma unroll
        for (int o = 1; o < 32; o <<= 1) {
            int y = __shfl_up_sync(0xffffffffu, x, o);
            if (lane >= o) x += y;
        }
        warp_sums[lane] = x;
    }
    __syncthreads();
    int run = ps - s + (w > 0 ? warp_sums[w - 1] : 0);
#pragma unroll
    for (int i = 0; i < 8; i++) {
        g_offsets[base + i] = run;
        g_cursor [base + i] = run;
        run += v[i];
    }
    if (t == 1023) g_offsets[NN] = run;
}
__global__ void k_fill(const int* __restrict__ ei) {
    int idx = blockIdx.x * blockDim.x + threadIdx.x;
    if (idx >= ET) return;
    int src, dst;
    if (idx < EE) { src = ei[idx]; dst = ei[EE + idx]; }
    else          { src = dst = idx - EE; }
    g_csr[atomicAdd(&g_cursor[dst], 1)] = src;
}

/* ---------------- mma.sync pure-fp16 GEMM (K = K1) ----------------------- */
#define BM   128
#define BN   128
#define BK   64
#define NST  3
#define NIT  16                  /* K1 / BK */
#define STR  36                  /* u32 stride per row (32 kpairs + 4 pad) */
#define A_U32 (BM * STR)
#define B_U32 (BN * STR)
#define STAGE_BYTES ((A_U32 + B_U32) * 4)
#define GEMM_SMEM (NST * STAGE_BYTES)

__global__ void __launch_bounds__(256, 2)
k_gemm_tc(const __half* __restrict__ A, const __half* __restrict__ B,
          __half* __restrict__ C, int Ntot)
{
    extern __shared__ char smem[];
    const uint32_t sb = smem_u32(smem);
    const int tid = threadIdx.x;
    const int lane = tid & 31;
    const int w = tid >> 5;
    const int wm = (w & 1) * 64;
    const int wn = (w >> 1) * 32;
    const int row0 = blockIdx.y * BM;
    const int col0 = blockIdx.x * BN;

    float acc[4][4][4];
#pragma unroll
    for (int i = 0; i < 4; i++)
#pragma unroll
        for (int j = 0; j < 4; j++)
#pragma unroll
            for (int q = 0; q < 4; q++) acc[i][j][q] = 0.f;

    const int msel = lane >> 3, within = lane & 7;
    const int a_r = (msel & 1) * 8 + within;
    const int a_c = (msel >> 1) * 4;
    const int b_r = (msel >> 1) * 8 + within;
    const int b_c = (msel & 1) * 4;

    auto load_chunk = [&](int ch) {
        int k0 = ch * BK;
        uint32_t sa = sb + (ch % NST) * STAGE_BYTES;
        uint32_t sB = sa + A_U32 * 4;
#pragma unroll
        for (int i = 0; i < 4; i++) {
            int lin = tid + i * 256, r = lin >> 3, j = lin & 7;
            CP16(sa + r * (STR * 4) + j * 16,
                 __cvta_generic_to_global(A + (size_t)(row0 + r) * K1 + k0 + j * 8));
        }
#pragma unroll
        for (int i = 0; i < 4; i++) {
            int lin = tid + i * 256, r = lin >> 3, j = lin & 7;
            CP16(sB + r * (STR * 4) + j * 16,
                 __cvta_generic_to_global(B + (size_t)(col0 + r) * K1 + k0 + j * 8));
        }
        CP_COMMIT();
    };

    load_chunk(0); load_chunk(1);

    for (int it = 0; it < NIT; it++) {
        if (it < NIT - 1) asm volatile("cp.async.wait_group 1;" ::: "memory");
        else              asm volatile("cp.async.wait_group 0;" ::: "memory");
        __syncthreads();
        if (it + 2 < NIT) load_chunk(it + 2);

        uint32_t sa = sb + (it % NST) * STAGE_BYTES;
        uint32_t sB = sa + A_U32 * 4;
#pragma unroll
        for (int kk = 0; kk < 4; kk++) {
            uint32_t af[4][4], bf[4][2];
#pragma unroll
            for (int mf = 0; mf < 4; mf++)
                ldsm4(af[mf], sa + ((wm + mf * 16 + a_r) * STR + kk * 8 + a_c) * 4);
#pragma unroll
            for (int p = 0; p < 2; p++) {
                uint32_t t4[4];
                ldsm4(t4, sB + ((wn + p * 16 + b_r) * STR + kk * 8 + b_c) * 4);
                bf[2 * p][0] = t4[0]; bf[2 * p][1] = t4[1];
                bf[2 * p + 1][0] = t4[2]; bf[2 * p + 1][1] = t4[3];
            }
#pragma unroll
            for (int mf = 0; mf < 4; mf++)
#pragma unroll
                for (int nf = 0; nf < 4; nf++)
                    mma16816(acc[mf][nf], af[mf], bf[nf]);
        }
    }

    const int r = lane >> 2, q = lane & 3;
#pragma unroll
    for (int mf = 0; mf < 4; mf++) {
        int rg = row0 + wm + mf * 16 + r;
#pragma unroll
        for (int nf = 0; nf < 4; nf++) {
            __half* p0 = C + (size_t)rg * Ntot + col0 + wn + nf * 8 + q * 2;
            *(__half2*)p0 = __halves2half2(__float2half(acc[mf][nf][0]), __float2half(acc[mf][nf][1]));
            *(__half2*)(p0 + (size_t)8 * Ntot) =
                __halves2half2(__float2half(acc[mf][nf][2]), __float2half(acc[mf][nf][3]));
        }
    }
}

/* ---------------- fused layer-1: warp per (node, head), 2-edge ILP -------- */
__global__ void __launch_bounds__(256)
k_fused1(const float* __restrict__ att, const float* __restrict__ bias)
{
    const int w = threadIdx.x >> 5;
    const int lane = threadIdx.x & 31;
    const int n = blockIdx.x * 2 + (w >> 2);
    const int h = w & 3;
    const int cA = h * 256 + lane * 4;
    const int cB = cA + 128;

    const __half* base1 = g_C1;
    const float4 xr0 = ldh4(&base1[(size_t)n * NT1 + 1024 + cA]);
    const float4 xr1 = ldh4(&base1[(size_t)n * NT1 + 1024 + cB]);
    const float4 at0 = *(const float4*)&att[cA];
    const float4 at1 = *(const float4*)&att[cB];

    float4 num0 = make_float4(0.f, 0.f, 0.f, 0.f);
    float4 num1 = make_float4(0.f, 0.f, 0.f, 0.f);
    float den = 0.f;
    const int beg = g_offsets[n], end = g_offsets[n + 1];

    auto score = [&](const float4& xl0, const float4& xl1) {
        float v0 = lrelu(xl0.x + xr0.x), v1 = lrelu(xl0.y + xr0.y);
        float v2 = lrelu(xl0.z + xr0.z), v3 = lrelu(xl0.w + xr0.w);
        float u0 = lrelu(xl1.x + xr1.x), u1 = lrelu(xl1.y + xr1.y);
        float u2 = lrelu(xl1.z + xr1.z), u3 = lrelu(xl1.w + xr1.w);
        return fmaf(v0, at0.x, fmaf(v1, at0.y, fmaf(v2, at0.z, v3 * at0.w)))
             + fmaf(u0, at1.x, fmaf(u1, at1.y, fmaf(u2, at1.z, u3 * at1.w)));
    };
    auto accum = [&](float ex, const float4& xl0, const float4& xl1) {
        den += ex;
        num0.x = fmaf(ex, xl0.x, num0.x); num0.y = fmaf(ex, xl0.y, num0.y);
        num0.z = fmaf(ex, xl0.z, num0.z); num0.w = fmaf(ex, xl0.w, num0.w);
        num1.x = fmaf(ex, xl1.x, num1.x); num1.y = fmaf(ex, xl1.y, num1.y);
        num1.z = fmaf(ex, xl1.z, num1.z); num1.w = fmaf(ex, xl1.w, num1.w);
    };

    int j = beg;
    for (; j + 1 < end; j += 2) {
        int s0 = g_csr[j], s1 = g_csr[j + 1];
        const __half* rowA = &base1[(size_t)s0 * NT1];
        const __half* rowB = &base1[(size_t)s1 * NT1];
        float4 a0 = ldh4(&rowA[cA]);
        float4 b0 = ldh4(&rowB[cA]);
        float4 a1 = ldh4(&rowA[cB]);
        float4 b1 = ldh4(&rowB[cB]);
        float pA = score(a0, a1);
        float pB = score(b0, b1);
#pragma unroll
        for (int o = 16; o > 0; o >>= 1) {           /* interleaved butterflies */
            pA += __shfl_xor_sync(0xffffffffu, pA, o);
            pB += __shfl_xor_sync(0xffffffffu, pB, o);
        }
        float exA = __expf(pA), exB = __expf(pB);
        accum(exA, a0, a1);
        accum(exB, b0, b1);
    }
    if (j < end) {
        int s0 = g_csr[j];
        const __half* rowA = &base1[(size_t)s0 * NT1];
        float4 a0 = ldh4(&rowA[cA]);
        float4 a1 = ldh4(&rowA[cB]);
        float pA = score(a0, a1);
#pragma unroll
        for (int o = 16; o > 0; o >>= 1)
            pA += __shfl_xor_sync(0xffffffffu, pA, o);
        accum(__expf(pA), a0, a1);
    }

    const float4 bA = *(const float4*)&bias[cA];
    const float4 bB = *(const float4*)&bias[cB];
    const float inv = 1.f / den;
    float r0 = fmaxf(fmaf(num0.x, inv, bA.x), 0.f);
    float r1 = fmaxf(fmaf(num0.y, inv, bA.y), 0.f);
    float r2 = fmaxf(fmaf(num0.z, inv, bA.z), 0.f);
    float r3 = fmaxf(fmaf(num0.w, inv, bA.w), 0.f);
    float s0 = fmaxf(fmaf(num1.x, inv, bB.x), 0.f);
    float s1 = fmaxf(fmaf(num1.y, inv, bB.y), 0.f);
    float s2 = fmaxf(fmaf(num1.z, inv, bB.z), 0.f);
    float s3 = fmaxf(fmaf(num1.w, inv, bB.w), 0.f);

    size_t baseA = (size_t)n * 1024 + cA;
    size_t baseB = (size_t)n * 1024 + cB;
    *(__half2*)&g_Ax2[baseA]     = __halves2half2(__float2half(r0), __float2half(r1));
    *(__half2*)&g_Ax2[baseA + 2] = __halves2half2(__float2half(r2), __float2half(r3));
    *(__half2*)&g_Ax2[baseB]     = __halves2half2(__float2half(s0), __float2half(s1));
    *(__half2*)&g_Ax2[baseB + 2] = __halves2half2(__float2half(s2), __float2half(s3));
}

/* ---------------- fused layer-2: warp per node, 2-edge ILP ---------------- */
__global__ void __launch_bounds__(256)
k_fused2(const float* __restrict__ att, const float* __restrict__ bias,
         float* __restrict__ out)
{
    const int w = threadIdx.x >> 5;
    const int lane = threadIdx.x & 31;
    const int n = blockIdx.x * 8 + w;
    const int cA = lane * 4;
    const int cB = cA + 128;

    const __half* base2 = g_C2;
    const float4 xr0 = ldh4(&base2[(size_t)n * NT2 + 256 + cA]);
    const float4 xr1 = ldh4(&base2[(size_t)n * NT2 + 256 + cB]);
    const float4 at0 = *(const float4*)&att[cA];
    const float4 at1 = *(const float4*)&att[cB];

    float4 num0 = make_float4(0.f, 0.f, 0.f, 0.f);
    float4 num1 = make_float4(0.f, 0.f, 0.f, 0.f);
    float den = 0.f;
    const int beg = g_offsets[n], end = g_offsets[n + 1];

    auto score = [&](const float4& xl0, const float4& xl1) {
        float v0 = lrelu(xl0.x + xr0.x), v1 = lrelu(xl0.y + xr0.y);
        float v2 = lrelu(xl0.z + xr0.z), v3 = lrelu(xl0.w + xr0.w);
        float u0 = lrelu(xl1.x + xr1.x), u1 = lrelu(xl1.y + xr1.y);
        float u2 = lrelu(xl1.z + xr1.z), u3 = lrelu(xl1.w + xr1.w);
        return fmaf(v0, at0.x, fmaf(v1, at0.y, fmaf(v2, at0.z, v3 * at0.w)))
             + fmaf(u0, at1.x, fmaf(u1, at1.y, fmaf(u2, at1.z, u3 * at1.w)));
    };
    auto accum = [&](float ex, const float4& xl0, const float4& xl1) {
        den += ex;
        num0.x = fmaf(ex, xl0.x, num0.x); num0.y = fmaf(ex, xl0.y, num0.y);
        num0.z = fmaf(ex, xl0.z, num0.z); num0.w = fmaf(ex, xl0.w, num0.w);
        num1.x = fmaf(ex, xl1.x, num1.x); num1.y = fmaf(ex, xl1.y, num1.y);
        num1.z = fmaf(ex, xl1.z, num1.z); num1.w = fmaf(ex, xl1.w, num1.w);
    };

    int j = beg;
    for (; j + 1 < end; j += 2) {
        int s0 = g_csr[j], s1 = g_csr[j + 1];
        const __half* rowA = &base2[(size_t)s0 * NT2];
        const __half* rowB = &base2[(size_t)s1 * NT2];
        float4 a0 = ldh4(&rowA[cA]);
        float4 b0 = ldh4(&rowB[cA]);
        float4 a1 = ldh4(&rowA[cB]);
        float4 b1 = ldh4(&rowB[cB]);
        float pA = score(a0, a1);
        float pB = score(b0, b1);
#pragma unroll
        for (int o = 16; o > 0; o >>= 1) {
            pA += __shfl_xor_sync(0xffffffffu, pA, o);
            pB += __shfl_xor_sync(0xffffffffu, pB, o);
        }
        float exA = __expf(pA), exB = __expf(pB);
        accum(exA, a0, a1);
        accum(exB, b0, b1);
    }
    if (j < end) {
        int s0 = g_csr[j];
        const __half* rowA = &base2[(size_t)s0 * NT2];
        float4 a0 = ldh4(&rowA[cA]);
        float4 a1 = ldh4(&rowA[cB]);
        float pA = score(a0, a1);
#pragma unroll
        for (int o = 16; o > 0; o >>= 1)
            pA += __shfl_xor_sync(0xffffffffu, pA, o);
        accum(__expf(pA), a0, a1);
    }

    const float4 bA = *(const float4*)&bias[cA];
    const float4 bB = *(const float4*)&bias[cB];
    const float inv = 1.f / den;
    float4 rA, rB;
    rA.x = fmaxf(fmaf(num0.x, inv, bA.x), 0.f);
    rA.y = fmaxf(fmaf(num0.y, inv, bA.y), 0.f);
    rA.z = fmaxf(fmaf(num0.z, inv, bA.z), 0.f);
    rA.w = fmaxf(fmaf(num0.w, inv, bA.w), 0.f);
    rB.x = fmaxf(fmaf(num1.x, inv, bB.x), 0.f);
    rB.y = fmaxf(fmaf(num1.y, inv, bB.y), 0.f);
    rB.z = fmaxf(fmaf(num1.z, inv, bB.z), 0.f);
    rB.w = fmaxf(fmaf(num1.w, inv, bB.w), 0.f);
    *(float4*)&out[(size_t)n * CC + cA] = rA;
    *(float4*)&out[(size_t)n * CC + cB] = rB;
}

/* ---------------- launch ---------------- */
extern "C" void kernel_launch(void* const* d_in, const int* in_sizes, int n_in,
                              void* d_out, int out_size)
{
    const float* x    = (const float*)d_in[0];
    const int*   ei   = (const int*)  d_in[1];
    const float* Wl1  = (const float*)d_in[2];
    const float* Wr1  = (const float*)d_in[3];
    const float* att1 = (const float*)d_in[4];
    const float* b1   = (const float*)d_in[5];
    const float* Wl2  = (const float*)d_in[6];
    const float* Wr2  = (const float*)d_in[7];
    const float* att2 = (const float*)d_in[8];
    const float* b2   = (const float*)d_in[9];
    float* out = (float*)d_out;

    __half *p_Ax1, *p_Bt1, *p_Ax2, *p_Bt2, *p_C1, *p_C2;
    cudaGetSymbolAddress((void**)&p_Ax1, g_Ax1);
    cudaGetSymbolAddress((void**)&p_Bt1, g_Bt1);
    cudaGetSymbolAddress((void**)&p_C1,  g_C1);
    cudaGetSymbolAddress((void**)&p_Ax2, g_Ax2);
    cudaGetSymbolAddress((void**)&p_Bt2, g_Bt2);
    cudaGetSymbolAddress((void**)&p_C2,  g_C2);

    cudaFuncSetAttribute(k_gemm_tc, cudaFuncAttributeMaxDynamicSharedMemorySize, GEMM_SMEM);

    /* merged prologue (splits + edge count) + CSR chain */
    k_prep<<<PREP_BLOCKS, 256>>>(x, Wl1, Wr1, Wl2, Wr2, ei);
    k_scan<<<1, 1024>>>();
    k_fill<<<(ET + 255) / 256, 256>>>(ei);

    /* layer 1 */
    k_gemm_tc<<<dim3(NT1 / BN, NN / BM), 256, GEMM_SMEM>>>(p_Ax1, p_Bt1, p_C1, NT1);
    k_fused1<<<NN / 2, 256>>>(att1, b1);

    /* layer 2 */
    k_gemm_tc<<<dim3(NT2 / BN, NN / BM), 256, GEMM_SMEM>>>(p_Ax2, p_Bt2, p_C2, NT2);
    k_fused2<<<NN / 8, 256>>>(att2, b2, out);
}